// round 11
// baseline (speedup 1.0000x reference)
#include <cuda_runtime.h>
#include <cuda_fp16.h>
#include <math.h>
#include <stdint.h>

#define TT     2048
#define HH     16
#define DQK    192
#define DNOPE  128
#define DROPE  64
#define DLORA  512
#define DV     128
#define ATT_SCALE 0.07216878364870323f   // 1/sqrt(192)

// ---------------- scratch (static __device__; no cudaMalloc allowed) --------
__device__ __half g_qh[HH * TT * DQK];         // fp16 hi (h,t,192)
__device__ __half g_ql[HH * TT * DQK];         // fp16 lo
__device__ __half g_kh[HH * TT * DQK];
__device__ __half g_kl[HH * TT * DQK];
__device__ __half g_vth[HH * DV * TT];         // fp16 hi V^T (h,v,t)
__device__ __half g_ach[TT * DLORA];           // kc hi (t,k)
__device__ __half g_acl[TT * DLORA];           // kc lo
__device__ __half g_wbh[HH * 256 * DLORA];     // weights hi (n,k), n=h*256+j
__device__ __half g_wbl[HH * 256 * DLORA];     // weights lo

// ---------------------------------------------------------------------------
// helpers
// ---------------------------------------------------------------------------
__device__ __forceinline__ void split2pack(float x, float y, uint32_t& hi, uint32_t& lo) {
    __half hx = __float2half_rn(x), hy = __float2half_rn(y);
    __half lx = __float2half_rn(x - __half2float(hx));
    __half ly = __float2half_rn(y - __half2float(hy));
    hi = (uint32_t)__half_as_ushort(hx) | ((uint32_t)__half_as_ushort(hy) << 16);
    lo = (uint32_t)__half_as_ushort(lx) | ((uint32_t)__half_as_ushort(ly) << 16);
}

__device__ __forceinline__ void mma16816(float* d, const uint32_t* a, const uint32_t* b) {
    asm volatile(
        "mma.sync.aligned.m16n8k16.row.col.f32.f16.f16.f32 "
        "{%0,%1,%2,%3}, {%4,%5,%6,%7}, {%8,%9}, {%0,%1,%2,%3};"
        : "+f"(d[0]), "+f"(d[1]), "+f"(d[2]), "+f"(d[3])
        : "r"(a[0]), "r"(a[1]), "r"(a[2]), "r"(a[3]), "r"(b[0]), "r"(b[1]));
}

// 16B-slot swizzle: conflict-free fragment staging
#define SWZ(s) ((s) ^ (((s) >> 2) & 7))

// ---------------------------------------------------------------------------
// Kernel A: kc (2048,512) fp32 -> g_ach/g_acl fp16 (same layout)
// ---------------------------------------------------------------------------
__global__ __launch_bounds__(256) void kcsplit_kernel(const float* __restrict__ kc) {
    int g = blockIdx.x * 256 + threadIdx.x;    // over elems/8
    size_t off = (size_t)g * 8;
    float4 a = *(const float4*)&kc[off];
    float4 b = *(const float4*)&kc[off + 4];
    float x[8] = {a.x, a.y, a.z, a.w, b.x, b.y, b.z, b.w};
    uint32_t ph[4], pl[4];
#pragma unroll
    for (int j = 0; j < 4; j++) split2pack(x[2 * j], x[2 * j + 1], ph[j], pl[j]);
    *(uint4*)&g_ach[off] = make_uint4(ph[0], ph[1], ph[2], ph[3]);
    *(uint4*)&g_acl[off] = make_uint4(pl[0], pl[1], pl[2], pl[3]);
}

// ---------------------------------------------------------------------------
// Kernel B1: wkv (512, 4096) cols h*256..h*256+128 -> g_wbh/g_wbl rows h*256+j
// ---------------------------------------------------------------------------
__global__ __launch_bounds__(256) void wkvsplit_kernel(const float* __restrict__ wkv) {
    __shared__ float ts[64][65];
    const int tid = threadIdx.x;
    const int k0 = blockIdx.x * 64;
    const int j0 = blockIdx.y * 64;
    const int h  = blockIdx.z;
#pragma unroll
    for (int i = 0; i < 16; i++) {
        int idx = tid + i * 256;
        int kk = idx >> 6, jj = idx & 63;
        ts[kk][jj] = wkv[(size_t)(k0 + kk) * (HH * 256) + h * 256 + j0 + jj];
    }
    __syncthreads();
#pragma unroll
    for (int i = 0; i < 16; i++) {
        int idx = tid + i * 256;
        int jj = idx >> 6, kk = idx & 63;
        float x = ts[kk][jj];
        __half hx = __float2half_rn(x);
        __half lx = __float2half_rn(x - __half2float(hx));
        size_t o = (size_t)(h * 256 + j0 + jj) * DLORA + k0 + kk;
        g_wbh[o] = hx;
        g_wbl[o] = lx;
    }
}

// ---------------------------------------------------------------------------
// Kernel B2: wuv (H,512,128) -> g_wbh/g_wbl rows h*256+128+j
// ---------------------------------------------------------------------------
__global__ __launch_bounds__(256) void wuvsplit_kernel(const float* __restrict__ wuv) {
    __shared__ float ts[64][65];
    const int tid = threadIdx.x;
    const int k0 = blockIdx.x * 64;
    const int j0 = blockIdx.y * 64;
    const int h  = blockIdx.z;
#pragma unroll
    for (int i = 0; i < 16; i++) {
        int idx = tid + i * 256;
        int kk = idx >> 6, jj = idx & 63;
        ts[kk][jj] = wuv[(size_t)(h * DLORA + k0 + kk) * DV + j0 + jj];
    }
    __syncthreads();
#pragma unroll
    for (int i = 0; i < 16; i++) {
        int idx = tid + i * 256;
        int jj = idx >> 6, kk = idx & 63;
        float x = ts[kk][jj];
        __half hx = __float2half_rn(x);
        __half lx = __float2half_rn(x - __half2float(hx));
        size_t o = (size_t)(h * 256 + 128 + j0 + jj) * DLORA + k0 + kk;
        g_wbh[o] = hx;
        g_wbl[o] = lx;
    }
}

// ---------------------------------------------------------------------------
// Kernel C: broadcast k_pe (split) into g_kh/g_kl[h][t][128:192]
// ---------------------------------------------------------------------------
__global__ __launch_bounds__(256) void pefill_kernel(const float* __restrict__ kpe) {
    int idx = blockIdx.x * 256 + threadIdx.x;
    if (idx >= HH * TT * DROPE) return;
    int r = idx & 63;
    int t = (idx >> 6) & (TT - 1);
    int h = idx >> 17;
    float x = kpe[t * DROPE + r];
    __half hx = __float2half_rn(x);
    __half lx = __float2half_rn(x - __half2float(hx));
    size_t o = (size_t)(h * TT + t) * DQK + DNOPE + r;
    g_kh[o] = hx;
    g_kl[o] = lx;
}

// ---------------------------------------------------------------------------
// Kernel D: prologue GEMM on HMMA, register-prefetch software pipeline.
// C(128m x 128n) = Ahi/lo @ Bhi/lo (K=512).
// ---------------------------------------------------------------------------
#define GA_H 0
#define GA_L 1024
#define GB_H 2048
#define GB_L 3072
#define GEMM_SMEM_BYTES 36864   // max(16KB staging, 128*144*2 V-transpose)

__global__ __launch_bounds__(256) void prolog_gemm_kernel() {
    __shared__ __align__(16) char smbuf[GEMM_SMEM_BYTES];
    uint32_t* smw = (uint32_t*)smbuf;
    const int tid = threadIdx.x;
    const int w = tid >> 5, lane = tid & 31;
    const int gr = lane >> 2, tg = lane & 3;
    const int laneSw = SWZ(lane);
    const int n0 = blockIdx.x * 128;
    const int m0 = blockIdx.y * 128;
    const int h = n0 >> 8;
    const bool isK = ((n0 & 255) == 0);
    const int wm = w >> 2, wn = w & 3;

    float C[4][4][4];
#pragma unroll
    for (int a = 0; a < 4; a++)
#pragma unroll
        for (int b = 0; b < 4; b++)
#pragma unroll
            for (int e = 0; e < 4; e++) C[a][b][e] = 0.f;

    const int rr = tid >> 1, kk0h = tid & 1;
    const int mt = rr >> 4, r16 = rr & 15;
    const int uA = r16 & 7;
    const int regA = (kk0h << 1) | (r16 >> 3);
    const int rowA = mt * 32;
    const int sA0 = rowA + SWZ(uA * 4 + 0);
    const int sA1 = rowA + SWZ(uA * 4 + 1);
    const int sA2 = rowA + SWZ(uA * 4 + 2);
    const int sA3 = rowA + SWZ(uA * 4 + 3);
    const int ntB = rr >> 3, uB = rr & 7, regB = kk0h;
    const int rowB = ntB * 32;
    const int sB0 = rowB + SWZ(uB * 4 + 0);
    const int sB1 = rowB + SWZ(uB * 4 + 1);
    const int sB2 = rowB + SWZ(uB * 4 + 2);
    const int sB3 = rowB + SWZ(uB * 4 + 3);

    const size_t aoff = (size_t)(m0 + rr) * DLORA + kk0h * 8;
    const size_t boff = (size_t)(n0 + rr) * DLORA + kk0h * 8;

    // ---- prefetch k0 = 0 ----
    uint4 ah = *(const uint4*)&g_ach[aoff];
    uint4 al = *(const uint4*)&g_acl[aoff];
    uint4 bh = *(const uint4*)&g_wbh[boff];
    uint4 bl = *(const uint4*)&g_wbl[boff];

    for (int k0 = 0; k0 < DLORA; k0 += 16) {
        __syncthreads();   // previous compute done reading smem
        smw[GA_H + sA0 * 4 + regA] = ah.x;
        smw[GA_H + sA1 * 4 + regA] = ah.y;
        smw[GA_H + sA2 * 4 + regA] = ah.z;
        smw[GA_H + sA3 * 4 + regA] = ah.w;
        smw[GA_L + sA0 * 4 + regA] = al.x;
        smw[GA_L + sA1 * 4 + regA] = al.y;
        smw[GA_L + sA2 * 4 + regA] = al.z;
        smw[GA_L + sA3 * 4 + regA] = al.w;
        smw[GB_H + sB0 * 2 + regB] = bh.x;
        smw[GB_H + sB1 * 2 + regB] = bh.y;
        smw[GB_H + sB2 * 2 + regB] = bh.z;
        smw[GB_H + sB3 * 2 + regB] = bh.w;
        smw[GB_L + sB0 * 2 + regB] = bl.x;
        smw[GB_L + sB1 * 2 + regB] = bl.y;
        smw[GB_L + sB2 * 2 + regB] = bl.z;
        smw[GB_L + sB3 * 2 + regB] = bl.w;
        __syncthreads();

        // ---- issue next chunk's loads (latency hidden under MMAs) ----
        if (k0 + 16 < DLORA) {
            ah = *(const uint4*)&g_ach[aoff + k0 + 16];
            al = *(const uint4*)&g_acl[aoff + k0 + 16];
            bh = *(const uint4*)&g_wbh[boff + k0 + 16];
            bl = *(const uint4*)&g_wbl[boff + k0 + 16];
        }

#pragma unroll
        for (int m2 = 0; m2 < 4; m2++) {
            uint4 aH4 = *(const uint4*)&smw[GA_H + ((wm * 4 + m2) * 32 + laneSw) * 4];
            uint4 aL4 = *(const uint4*)&smw[GA_L + ((wm * 4 + m2) * 32 + laneSw) * 4];
            uint32_t aH[4] = {aH4.x, aH4.y, aH4.z, aH4.w};
            uint32_t aL[4] = {aL4.x, aL4.y, aL4.z, aL4.w};
#pragma unroll
            for (int n2 = 0; n2 < 4; n2++) {
                uint2 bH2 = *(const uint2*)&smw[GB_H + ((wn * 4 + n2) * 32 + laneSw) * 2];
                uint2 bL2 = *(const uint2*)&smw[GB_L + ((wn * 4 + n2) * 32 + laneSw) * 2];
                uint32_t bH[2] = {bH2.x, bH2.y};
                uint32_t bL[2] = {bL2.x, bL2.y};
                mma16816(C[m2][n2], aH, bH);
                mma16816(C[m2][n2], aL, bH);
                mma16816(C[m2][n2], aH, bL);
            }
        }
    }

    __syncthreads();
    if (isK) {
#pragma unroll
        for (int m2 = 0; m2 < 4; m2++) {
            int row = m0 + wm * 64 + m2 * 16 + gr;
#pragma unroll
            for (int n2 = 0; n2 < 4; n2++) {
                int d = wn * 32 + n2 * 8 + 2 * tg;
                uint32_t hi, lo;
                split2pack(C[m2][n2][0], C[m2][n2][1], hi, lo);
                *(uint32_t*)&g_kh[(size_t)(h * TT + row) * DQK + d] = hi;
                *(uint32_t*)&g_kl[(size_t)(h * TT + row) * DQK + d] = lo;
                split2pack(C[m2][n2][2], C[m2][n2][3], hi, lo);
                *(uint32_t*)&g_kh[(size_t)(h * TT + row + 8) * DQK + d] = hi;
                *(uint32_t*)&g_kl[(size_t)(h * TT + row + 8) * DQK + d] = lo;
            }
        }
    } else {
        __half* sC = (__half*)smbuf;   // [128 v][144]
#pragma unroll
        for (int m2 = 0; m2 < 4; m2++) {
            int t = wm * 64 + m2 * 16 + gr;
#pragma unroll
            for (int n2 = 0; n2 < 4; n2++) {
                int v = wn * 32 + n2 * 8 + 2 * tg;
                sC[v * 144 + t]           = __float2half_rn(C[m2][n2][0]);
                sC[(v + 1) * 144 + t]     = __float2half_rn(C[m2][n2][1]);
                sC[v * 144 + t + 8]       = __float2half_rn(C[m2][n2][2]);
                sC[(v + 1) * 144 + t + 8] = __float2half_rn(C[m2][n2][3]);
            }
        }
        __syncthreads();
#pragma unroll
        for (int i = 0; i < 8; i++) {
            int idx = tid + i * 256;
            int vv = idx >> 4, tb = (idx & 15) * 8;
            uint4 val = *(const uint4*)&sC[vv * 144 + tb];
            *(uint4*)&g_vth[(size_t)(h * DV + vv) * TT + m0 + tb] = val;
        }
    }
}

// ---------------------------------------------------------------------------
// Kernel E: q (t,h,192) fp32 -> g_qh/g_ql (h,t,192) fp16
// ---------------------------------------------------------------------------
__global__ __launch_bounds__(256) void qsplit_kernel(const float* __restrict__ q) {
    int g = blockIdx.x * 256 + threadIdx.x;   // over elems/8
    int u = g % 24;
    int th = g / 24;
    int h = th & 15;
    int t = th >> 4;
    int d8 = u * 8;
    float4 a = *(const float4*)&q[(size_t)(t * HH + h) * DQK + d8];
    float4 b = *(const float4*)&q[(size_t)(t * HH + h) * DQK + d8 + 4];
    float x[8] = {a.x, a.y, a.z, a.w, b.x, b.y, b.z, b.w};
    uint32_t ph[4], pl[4];
#pragma unroll
    for (int j = 0; j < 4; j++) split2pack(x[2 * j], x[2 * j + 1], ph[j], pl[j]);
    size_t o = (size_t)(h * TT + t) * DQK + d8;
    *(uint4*)&g_qh[o] = make_uint4(ph[0], ph[1], ph[2], ph[3]);
    *(uint4*)&g_ql[o] = make_uint4(pl[0], pl[1], pl[2], pl[3]);
}

// ---------------------------------------------------------------------------
// Kernel F: flash attention on mma.sync (HMMA). q-tile 128, k-tile 64.
// Double-buffered K/V staging: stage(sb+1) overlaps compute(sb).
// ---------------------------------------------------------------------------
#define SQH 0
#define SQL 12288
#define KV0 24576          // buffer 0 base (words)
#define KVSZ 16384         // one K/V buffer: KH 6144 | KL 6144 | VH 4096
#define KH_OFF 0
#define KL_OFF 6144
#define VH_OFF 12288
#define FLASH_SMEM_BYTES ((KV0 + 2 * KVSZ) * 4)   // 229376 bytes

__global__ __launch_bounds__(256, 1) void flash_mma_kernel(float* __restrict__ out) {
    extern __shared__ uint32_t smw[];
    const int tid = threadIdx.x;
    const int w = tid >> 5, lane = tid & 31;
    const int gr = lane >> 2, tg = lane & 3;
    const int laneSw = SWZ(lane);
    const int id = blockIdx.x;
    const int h = id & 15, qb = 15 - (id >> 4);   // heaviest q-tiles first
    const int t0 = qb * 128;
    const int nsteps = 2 * qb + 2;

    // ---- stage Q fragments (once per CTA) ----
#pragma unroll
    for (int i = 0; i < 12; i++) {
        int idx = tid + i * 256;
        int rr = idx / 24, u24 = idx % 24;
        int ch = u24 >> 1, kk0h = u24 & 1;
        int mt = rr >> 4, r16 = rr & 15;
        int u = r16 & 7;
        int reg = (kk0h << 1) | (r16 >> 3);
        int row = (ch * 8 + mt) * 32, cx = ch & 7;
        int s0_ = row + (SWZ(u * 4 + 0) ^ cx);
        int s1_ = row + (SWZ(u * 4 + 1) ^ cx);
        int s2_ = row + (SWZ(u * 4 + 2) ^ cx);
        int s3_ = row + (SWZ(u * 4 + 3) ^ cx);
        size_t go = (size_t)(h * TT + t0 + rr) * DQK + ch * 16 + kk0h * 8;
        uint4 vh = *(const uint4*)&g_qh[go];
        uint4 vl = *(const uint4*)&g_ql[go];
        smw[SQH + s0_ * 4 + reg] = vh.x;
        smw[SQH + s1_ * 4 + reg] = vh.y;
        smw[SQH + s2_ * 4 + reg] = vh.z;
        smw[SQH + s3_ * 4 + reg] = vh.w;
        smw[SQL + s0_ * 4 + reg] = vl.x;
        smw[SQL + s1_ * 4 + reg] = vl.y;
        smw[SQL + s2_ * 4 + reg] = vl.z;
        smw[SQL + s3_ * 4 + reg] = vl.w;
    }

    // staging invariants (per thread)
    const int sK_sr = (tid * 6) / 256 >= 0 ? 0 : 0;   // (placeholder, unused)

    // ---- stage K/V for step sb into buffer base kb0 ----
    auto stageKV = [&](int s0, uint32_t kb0) {
#pragma unroll
        for (int i = 0; i < 6; i++) {
            int idx = tid + i * 256;
            int sr = idx / 24, u24 = idx % 24;
            int ch = u24 >> 1, kk0h = u24 & 1;
            int nt = sr >> 3, u = sr & 7;
            int reg = kk0h;
            int row = (ch * 8 + nt) * 32, cx = ch & 7;
            int s0_ = row + (SWZ(u * 4 + 0) ^ cx);
            int s1_ = row + (SWZ(u * 4 + 1) ^ cx);
            int s2_ = row + (SWZ(u * 4 + 2) ^ cx);
            int s3_ = row + (SWZ(u * 4 + 3) ^ cx);
            size_t go = (size_t)(h * TT + s0 + sr) * DQK + ch * 16 + kk0h * 8;
            uint4 vh = *(const uint4*)&g_kh[go];
            uint4 vl = *(const uint4*)&g_kl[go];
            smw[kb0 + KH_OFF + s0_ * 2 + reg] = vh.x;
            smw[kb0 + KH_OFF + s1_ * 2 + reg] = vh.y;
            smw[kb0 + KH_OFF + s2_ * 2 + reg] = vh.z;
            smw[kb0 + KH_OFF + s3_ * 2 + reg] = vh.w;
            smw[kb0 + KL_OFF + s0_ * 2 + reg] = vl.x;
            smw[kb0 + KL_OFF + s1_ * 2 + reg] = vl.y;
            smw[kb0 + KL_OFF + s2_ * 2 + reg] = vl.z;
            smw[kb0 + KL_OFF + s3_ * 2 + reg] = vl.w;
        }
#pragma unroll
        for (int i = 0; i < 4; i++) {
            int idx = tid + i * 256;
            int v = idx >> 3, u8 = idx & 7;
            int ch = u8 >> 1, kk0h = u8 & 1;
            int nt = v >> 3, u = v & 7;
            int reg = kk0h;
            int row = (ch * 16 + nt) * 32, cx = ch;
            int s0_ = row + (SWZ(u * 4 + 0) ^ cx);
            int s1_ = row + (SWZ(u * 4 + 1) ^ cx);
            int s2_ = row + (SWZ(u * 4 + 2) ^ cx);
            int s3_ = row + (SWZ(u * 4 + 3) ^ cx);
            size_t go = (size_t)(h * DV + v) * TT + s0 + ch * 16 + kk0h * 8;
            uint4 vv = *(const uint4*)&g_vth[go];
            smw[kb0 + VH_OFF + s0_ * 2 + reg] = vv.x;
            smw[kb0 + VH_OFF + s1_ * 2 + reg] = vv.y;
            smw[kb0 + VH_OFF + s2_ * 2 + reg] = vv.z;
            smw[kb0 + VH_OFF + s3_ * 2 + reg] = vv.w;
        }
    };

    float mA = -1.0e30f, mB = -1.0e30f, lA = 0.f, lB = 0.f;
    float O[16][4];
#pragma unroll
    for (int n = 0; n < 16; n++)
#pragma unroll
        for (int e = 0; e < 4; e++) O[n][e] = 0.f;

    stageKV(0, KV0);   // prologue stage into buffer 0

    for (int sb = 0; sb < nsteps; sb++) {
        const int s0 = sb * 64;
        const uint32_t cb = KV0 + (uint32_t)(sb & 1) * KVSZ;
        __syncthreads();   // staging(sb) complete; compute(sb-1) done

        // ---- stage next step into the other buffer (overlaps compute) ----
        if (sb + 1 < nsteps)
            stageKV(s0 + 64, KV0 + (uint32_t)((sb + 1) & 1) * KVSZ);

        if (s0 > t0 + w * 16 + 15) continue;   // warp tile fully masked

        // ---- S = Q K^T ----
        float S[8][4];
#pragma unroll
        for (int n = 0; n < 8; n++)
#pragma unroll
            for (int e = 0; e < 4; e++) S[n][e] = 0.f;

#pragma unroll 1
        for (int ch = 0; ch < 12; ch++) {
            int lsw = laneSw ^ (ch & 7);
            uint32_t ab = (uint32_t)(((ch * 8 + w) * 32 + lsw) * 4);
            uint4 aH4 = *(const uint4*)&smw[SQH + ab];
            uint4 aL4 = *(const uint4*)&smw[SQL + ab];
            uint32_t aH[4] = {aH4.x, aH4.y, aH4.z, aH4.w};
            uint32_t aL[4] = {aL4.x, aL4.y, aL4.z, aL4.w};
#pragma unroll
            for (int nt = 0; nt < 8; nt++) {
                uint32_t kb = cb + KH_OFF + (uint32_t)(((ch * 8 + nt) * 32 + lsw) * 2);
                uint2 bH = *(const uint2*)&smw[kb];
                uint32_t bh[2] = {bH.x, bH.y};
                mma16816(S[nt], aH, bh);
                mma16816(S[nt], aL, bh);
                uint2 bL = *(const uint2*)&smw[cb + KL_OFF +
                                               (uint32_t)(((ch * 8 + nt) * 32 + lsw) * 2)];
                uint32_t bl[2] = {bL.x, bL.y};
                mma16816(S[nt], aH, bl);
            }
        }

        // ---- scale + causal mask ----
        const int rowA = t0 + w * 16 + gr;
        const bool msk = (s0 + 63 > rowA);
#pragma unroll
        for (int nt = 0; nt < 8; nt++) {
            int col = s0 + nt * 8 + 2 * tg;
#pragma unroll
            for (int e = 0; e < 2; e++) {
                float xA = S[nt][e] * ATT_SCALE;
                float xB = S[nt][2 + e] * ATT_SCALE;
                if (msk) {
                    if (col + e > rowA) xA = -1.0e30f;
                    if (col + e > rowA + 8) xB = -1.0e30f;
                }
                S[nt][e] = xA;
                S[nt][2 + e] = xB;
            }
        }

        // ---- online softmax ----
        float pmA = -1.0e30f, pmB = -1.0e30f;
#pragma unroll
        for (int nt = 0; nt < 8; nt++) {
            pmA = fmaxf(pmA, fmaxf(S[nt][0], S[nt][1]));
            pmB = fmaxf(pmB, fmaxf(S[nt][2], S[nt][3]));
        }
        pmA = fmaxf(pmA, __shfl_xor_sync(0xffffffffu, pmA, 1));
        pmA = fmaxf(pmA, __shfl_xor_sync(0xffffffffu, pmA, 2));
        pmB = fmaxf(pmB, __shfl_xor_sync(0xffffffffu, pmB, 1));
        pmB = fmaxf(pmB, __shfl_xor_sync(0xffffffffu, pmB, 2));
        float mnA = fmaxf(mA, pmA), mnB = fmaxf(mB, pmB);
        float aAf = __expf(mA - mnA), aBf = __expf(mB - mnB);
        float sA = 0.f, sB = 0.f;
#pragma unroll
        for (int nt = 0; nt < 8; nt++) {
            S[nt][0] = __expf(S[nt][0] - mnA);
            S[nt][1] = __expf(S[nt][1] - mnA);
            S[nt][2] = __expf(S[nt][2] - mnB);
            S[nt][3] = __expf(S[nt][3] - mnB);
            sA += S[nt][0] + S[nt][1];
            sB += S[nt][2] + S[nt][3];
        }
        sA += __shfl_xor_sync(0xffffffffu, sA, 1);
        sA += __shfl_xor_sync(0xffffffffu, sA, 2);
        sB += __shfl_xor_sync(0xffffffffu, sB, 1);
        sB += __shfl_xor_sync(0xffffffffu, sB, 2);
        lA = lA * aAf + sA; mA = mnA;
        lB = lB * aBf + sB; mB = mnB;
#pragma unroll
        for (int n = 0; n < 16; n++) {
            O[n][0] *= aAf; O[n][1] *= aAf;
            O[n][2] *= aBf; O[n][3] *= aBf;
        }

        // ---- O += P V ----
#pragma unroll 1
        for (int c = 0; c < 4; c++) {
            uint32_t aPh[4], aPl[4];
#pragma unroll
            for (int q2 = 0; q2 < 2; q2++)
#pragma unroll
                for (int pr = 0; pr < 2; pr++)
                    split2pack(S[2 * c + q2][pr * 2], S[2 * c + q2][pr * 2 + 1],
                               aPh[q2 * 2 + pr], aPl[q2 * 2 + pr]);
            int lswv = laneSw ^ c;
#pragma unroll
            for (int nt = 0; nt < 16; nt++) {
                uint32_t vb = cb + VH_OFF + (uint32_t)(((c * 16 + nt) * 32 + lswv) * 2);
                uint2 bV = *(const uint2*)&smw[vb];
                uint32_t b2[2] = {bV.x, bV.y};
                mma16816(O[nt], aPh, b2);
                mma16816(O[nt], aPl, b2);
            }
        }
    }

    // ---- epilogue ----
    const float iA = 1.f / lA, iB = 1.f / lB;
    const int rowA = t0 + w * 16 + gr;
#pragma unroll
    for (int nt = 0; nt < 16; nt++) {
        int col = h * DV + nt * 8 + 2 * tg;
        *(float2*)&out[(size_t)rowA * (HH * DV) + col] =
            make_float2(O[nt][0] * iA, O[nt][1] * iA);
        *(float2*)&out[(size_t)(rowA + 8) * (HH * DV) + col] =
            make_float2(O[nt][2] * iB, O[nt][3] * iB);
    }
}

// ---------------------------------------------------------------------------
extern "C" void kernel_launch(void* const* d_in, const int* in_sizes, int n_in,
                              void* d_out, int out_size) {
    const float* q   = (const float*)d_in[0];   // (T, H, 192)
    const float* kc  = (const float*)d_in[1];   // (T, 512)
    const float* kpe = (const float*)d_in[2];   // (T, 64)
    const float* wkv = (const float*)d_in[3];   // (512, 4096)
    const float* wuv = (const float*)d_in[4];   // (H, 512, 128)
    float* out = (float*)d_out;                 // (T, 2048)

    kcsplit_kernel<<<TT * DLORA / 8 / 256, 256>>>(kc);
    wkvsplit_kernel<<<dim3(8, 2, 16), 256>>>(wkv);
    wuvsplit_kernel<<<dim3(8, 2, 16), 256>>>(wuv);
    prolog_gemm_kernel<<<dim3(32, 16), 256>>>();
    pefill_kernel<<<(HH * TT * DROPE + 255) / 256, 256>>>(kpe);
    qsplit_kernel<<<HH * TT * DQK / 8 / 256, 256>>>(q);

    cudaFuncSetAttribute(flash_mma_kernel, cudaFuncAttributeMaxDynamicSharedMemorySize,
                         FLASH_SMEM_BYTES);
    flash_mma_kernel<<<256, 256, FLASH_SMEM_BYTES>>>(out);
}

// round 12
// speedup vs baseline: 1.0587x; 1.0587x over previous
#include <cuda_runtime.h>
#include <cuda_fp16.h>
#include <math.h>
#include <stdint.h>

#define TT     2048
#define HH     16
#define DQK    192
#define DNOPE  128
#define DROPE  64
#define DLORA  512
#define DV     128
#define ATT_SCALE 0.07216878364870323f   // 1/sqrt(192)

// ---------------- scratch (static __device__; no cudaMalloc allowed) --------
__device__ __half g_qh[HH * TT * DQK];         // fp16 hi (h,t,192)
__device__ __half g_ql[HH * TT * DQK];         // fp16 lo
__device__ __half g_kh[HH * TT * DQK];
__device__ __half g_kl[HH * TT * DQK];
__device__ __half g_vth[HH * DV * TT];         // fp16 hi V^T (h,v,t)
__device__ __half g_ach[TT * DLORA];           // kc hi (t,k)
__device__ __half g_acl[TT * DLORA];           // kc lo
__device__ __half g_wbh[HH * 256 * DLORA];     // weights hi (n,k), n=h*256+j
__device__ __half g_wbl[HH * 256 * DLORA];     // weights lo

// ---------------------------------------------------------------------------
// helpers
// ---------------------------------------------------------------------------
__device__ __forceinline__ void split2pack(float x, float y, uint32_t& hi, uint32_t& lo) {
    __half hx = __float2half_rn(x), hy = __float2half_rn(y);
    __half lx = __float2half_rn(x - __half2float(hx));
    __half ly = __float2half_rn(y - __half2float(hy));
    hi = (uint32_t)__half_as_ushort(hx) | ((uint32_t)__half_as_ushort(hy) << 16);
    lo = (uint32_t)__half_as_ushort(lx) | ((uint32_t)__half_as_ushort(ly) << 16);
}

__device__ __forceinline__ void mma16816(float* d, const uint32_t* a, const uint32_t* b) {
    asm volatile(
        "mma.sync.aligned.m16n8k16.row.col.f32.f16.f16.f32 "
        "{%0,%1,%2,%3}, {%4,%5,%6,%7}, {%8,%9}, {%0,%1,%2,%3};"
        : "+f"(d[0]), "+f"(d[1]), "+f"(d[2]), "+f"(d[3])
        : "r"(a[0]), "r"(a[1]), "r"(a[2]), "r"(a[3]), "r"(b[0]), "r"(b[1]));
}

// 16B-slot swizzle: conflict-free fragment staging
#define SWZ(s) ((s) ^ (((s) >> 2) & 7))

// ---------------------------------------------------------------------------
// Kernel A: kc (2048,512) fp32 -> g_ach/g_acl fp16 (same layout)
// ---------------------------------------------------------------------------
__global__ __launch_bounds__(256) void kcsplit_kernel(const float* __restrict__ kc) {
    int g = blockIdx.x * 256 + threadIdx.x;    // over elems/8
    size_t off = (size_t)g * 8;
    float4 a = *(const float4*)&kc[off];
    float4 b = *(const float4*)&kc[off + 4];
    float x[8] = {a.x, a.y, a.z, a.w, b.x, b.y, b.z, b.w};
    uint32_t ph[4], pl[4];
#pragma unroll
    for (int j = 0; j < 4; j++) split2pack(x[2 * j], x[2 * j + 1], ph[j], pl[j]);
    *(uint4*)&g_ach[off] = make_uint4(ph[0], ph[1], ph[2], ph[3]);
    *(uint4*)&g_acl[off] = make_uint4(pl[0], pl[1], pl[2], pl[3]);
}

// ---------------------------------------------------------------------------
// Kernel B1: wkv (512, 4096) cols h*256..h*256+128 -> g_wbh/g_wbl rows h*256+j
// ---------------------------------------------------------------------------
__global__ __launch_bounds__(256) void wkvsplit_kernel(const float* __restrict__ wkv) {
    __shared__ float ts[64][65];
    const int tid = threadIdx.x;
    const int k0 = blockIdx.x * 64;
    const int j0 = blockIdx.y * 64;
    const int h  = blockIdx.z;
#pragma unroll
    for (int i = 0; i < 16; i++) {
        int idx = tid + i * 256;
        int kk = idx >> 6, jj = idx & 63;
        ts[kk][jj] = wkv[(size_t)(k0 + kk) * (HH * 256) + h * 256 + j0 + jj];
    }
    __syncthreads();
#pragma unroll
    for (int i = 0; i < 16; i++) {
        int idx = tid + i * 256;
        int jj = idx >> 6, kk = idx & 63;
        float x = ts[kk][jj];
        __half hx = __float2half_rn(x);
        __half lx = __float2half_rn(x - __half2float(hx));
        size_t o = (size_t)(h * 256 + j0 + jj) * DLORA + k0 + kk;
        g_wbh[o] = hx;
        g_wbl[o] = lx;
    }
}

// ---------------------------------------------------------------------------
// Kernel B2: wuv (H,512,128) -> g_wbh/g_wbl rows h*256+128+j
// ---------------------------------------------------------------------------
__global__ __launch_bounds__(256) void wuvsplit_kernel(const float* __restrict__ wuv) {
    __shared__ float ts[64][65];
    const int tid = threadIdx.x;
    const int k0 = blockIdx.x * 64;
    const int j0 = blockIdx.y * 64;
    const int h  = blockIdx.z;
#pragma unroll
    for (int i = 0; i < 16; i++) {
        int idx = tid + i * 256;
        int kk = idx >> 6, jj = idx & 63;
        ts[kk][jj] = wuv[(size_t)(h * DLORA + k0 + kk) * DV + j0 + jj];
    }
    __syncthreads();
#pragma unroll
    for (int i = 0; i < 16; i++) {
        int idx = tid + i * 256;
        int jj = idx >> 6, kk = idx & 63;
        float x = ts[kk][jj];
        __half hx = __float2half_rn(x);
        __half lx = __float2half_rn(x - __half2float(hx));
        size_t o = (size_t)(h * 256 + 128 + j0 + jj) * DLORA + k0 + kk;
        g_wbh[o] = hx;
        g_wbl[o] = lx;
    }
}

// ---------------------------------------------------------------------------
// Kernel C: broadcast k_pe (split) into g_kh/g_kl[h][t][128:192]
// ---------------------------------------------------------------------------
__global__ __launch_bounds__(256) void pefill_kernel(const float* __restrict__ kpe) {
    int idx = blockIdx.x * 256 + threadIdx.x;
    if (idx >= HH * TT * DROPE) return;
    int r = idx & 63;
    int t = (idx >> 6) & (TT - 1);
    int h = idx >> 17;
    float x = kpe[t * DROPE + r];
    __half hx = __float2half_rn(x);
    __half lx = __float2half_rn(x - __half2float(hx));
    size_t o = (size_t)(h * TT + t) * DQK + DNOPE + r;
    g_kh[o] = hx;
    g_kl[o] = lx;
}

// ---------------------------------------------------------------------------
// Kernel D: prologue GEMM on HMMA. C(128m x 128n) = Ahi/lo @ Bhi/lo (K=512).
// B-fragments hoisted out of the m2 loop (smem traffic 448 -> 256 B/lane/step).
// ---------------------------------------------------------------------------
#define GA_H 0
#define GA_L 1024
#define GB_H 2048
#define GB_L 3072
#define GEMM_SMEM_BYTES 36864   // max(16KB staging, 128*144*2 V-transpose)

__global__ __launch_bounds__(256) void prolog_gemm_kernel() {
    __shared__ __align__(16) char smbuf[GEMM_SMEM_BYTES];
    uint32_t* smw = (uint32_t*)smbuf;
    const int tid = threadIdx.x;
    const int w = tid >> 5, lane = tid & 31;
    const int gr = lane >> 2, tg = lane & 3;
    const int laneSw = SWZ(lane);
    const int n0 = blockIdx.x * 128;
    const int m0 = blockIdx.y * 128;
    const int h = n0 >> 8;
    const bool isK = ((n0 & 255) == 0);
    const int wm = w >> 2, wn = w & 3;

    float C[4][4][4];
#pragma unroll
    for (int a = 0; a < 4; a++)
#pragma unroll
        for (int b = 0; b < 4; b++)
#pragma unroll
            for (int e = 0; e < 4; e++) C[a][b][e] = 0.f;

    const int rr = tid >> 1, kk0h = tid & 1;
    const int mt = rr >> 4, r16 = rr & 15;
    const int uA = r16 & 7;
    const int regA = (kk0h << 1) | (r16 >> 3);
    const int rowA = mt * 32;
    const int sA0 = rowA + SWZ(uA * 4 + 0);
    const int sA1 = rowA + SWZ(uA * 4 + 1);
    const int sA2 = rowA + SWZ(uA * 4 + 2);
    const int sA3 = rowA + SWZ(uA * 4 + 3);
    const int ntB = rr >> 3, uB = rr & 7, regB = kk0h;
    const int rowB = ntB * 32;
    const int sB0 = rowB + SWZ(uB * 4 + 0);
    const int sB1 = rowB + SWZ(uB * 4 + 1);
    const int sB2 = rowB + SWZ(uB * 4 + 2);
    const int sB3 = rowB + SWZ(uB * 4 + 3);

    const size_t aoff = (size_t)(m0 + rr) * DLORA + kk0h * 8;
    const size_t boff = (size_t)(n0 + rr) * DLORA + kk0h * 8;

    // ---- prefetch k0 = 0 ----
    uint4 ah = *(const uint4*)&g_ach[aoff];
    uint4 al = *(const uint4*)&g_acl[aoff];
    uint4 bh = *(const uint4*)&g_wbh[boff];
    uint4 bl = *(const uint4*)&g_wbl[boff];

    for (int k0 = 0; k0 < DLORA; k0 += 16) {
        __syncthreads();   // previous compute done reading smem
        smw[GA_H + sA0 * 4 + regA] = ah.x;
        smw[GA_H + sA1 * 4 + regA] = ah.y;
        smw[GA_H + sA2 * 4 + regA] = ah.z;
        smw[GA_H + sA3 * 4 + regA] = ah.w;
        smw[GA_L + sA0 * 4 + regA] = al.x;
        smw[GA_L + sA1 * 4 + regA] = al.y;
        smw[GA_L + sA2 * 4 + regA] = al.z;
        smw[GA_L + sA3 * 4 + regA] = al.w;
        smw[GB_H + sB0 * 2 + regB] = bh.x;
        smw[GB_H + sB1 * 2 + regB] = bh.y;
        smw[GB_H + sB2 * 2 + regB] = bh.z;
        smw[GB_H + sB3 * 2 + regB] = bh.w;
        smw[GB_L + sB0 * 2 + regB] = bl.x;
        smw[GB_L + sB1 * 2 + regB] = bl.y;
        smw[GB_L + sB2 * 2 + regB] = bl.z;
        smw[GB_L + sB3 * 2 + regB] = bl.w;
        __syncthreads();

        // ---- issue next chunk's loads (latency hidden under MMAs) ----
        if (k0 + 16 < DLORA) {
            ah = *(const uint4*)&g_ach[aoff + k0 + 16];
            al = *(const uint4*)&g_acl[aoff + k0 + 16];
            bh = *(const uint4*)&g_wbh[boff + k0 + 16];
            bl = *(const uint4*)&g_wbl[boff + k0 + 16];
        }

        // ---- load all B fragments once (reused across the 4 m2 tiles) ----
        uint32_t fBH[4][2], fBL[4][2];
#pragma unroll
        for (int n2 = 0; n2 < 4; n2++) {
            uint2 t1 = *(const uint2*)&smw[GB_H + ((wn * 4 + n2) * 32 + laneSw) * 2];
            uint2 t2 = *(const uint2*)&smw[GB_L + ((wn * 4 + n2) * 32 + laneSw) * 2];
            fBH[n2][0] = t1.x; fBH[n2][1] = t1.y;
            fBL[n2][0] = t2.x; fBL[n2][1] = t2.y;
        }

#pragma unroll
        for (int m2 = 0; m2 < 4; m2++) {
            uint4 aH4 = *(const uint4*)&smw[GA_H + ((wm * 4 + m2) * 32 + laneSw) * 4];
            uint4 aL4 = *(const uint4*)&smw[GA_L + ((wm * 4 + m2) * 32 + laneSw) * 4];
            uint32_t aH[4] = {aH4.x, aH4.y, aH4.z, aH4.w};
            uint32_t aL[4] = {aL4.x, aL4.y, aL4.z, aL4.w};
#pragma unroll
            for (int n2 = 0; n2 < 4; n2++) {
                mma16816(C[m2][n2], aH, fBH[n2]);
                mma16816(C[m2][n2], aL, fBH[n2]);
                mma16816(C[m2][n2], aH, fBL[n2]);
            }
        }
    }

    __syncthreads();
    if (isK) {
#pragma unroll
        for (int m2 = 0; m2 < 4; m2++) {
            int row = m0 + wm * 64 + m2 * 16 + gr;
#pragma unroll
            for (int n2 = 0; n2 < 4; n2++) {
                int d = wn * 32 + n2 * 8 + 2 * tg;
                uint32_t hi, lo;
                split2pack(C[m2][n2][0], C[m2][n2][1], hi, lo);
                *(uint32_t*)&g_kh[(size_t)(h * TT + row) * DQK + d] = hi;
                *(uint32_t*)&g_kl[(size_t)(h * TT + row) * DQK + d] = lo;
                split2pack(C[m2][n2][2], C[m2][n2][3], hi, lo);
                *(uint32_t*)&g_kh[(size_t)(h * TT + row + 8) * DQK + d] = hi;
                *(uint32_t*)&g_kl[(size_t)(h * TT + row + 8) * DQK + d] = lo;
            }
        }
    } else {
        __half* sC = (__half*)smbuf;   // [128 v][144]
#pragma unroll
        for (int m2 = 0; m2 < 4; m2++) {
            int t = wm * 64 + m2 * 16 + gr;
#pragma unroll
            for (int n2 = 0; n2 < 4; n2++) {
                int v = wn * 32 + n2 * 8 + 2 * tg;
                sC[v * 144 + t]           = __float2half_rn(C[m2][n2][0]);
                sC[(v + 1) * 144 + t]     = __float2half_rn(C[m2][n2][1]);
                sC[v * 144 + t + 8]       = __float2half_rn(C[m2][n2][2]);
                sC[(v + 1) * 144 + t + 8] = __float2half_rn(C[m2][n2][3]);
            }
        }
        __syncthreads();
#pragma unroll
        for (int i = 0; i < 8; i++) {
            int idx = tid + i * 256;
            int vv = idx >> 4, tb = (idx & 15) * 8;
            uint4 val = *(const uint4*)&sC[vv * 144 + tb];
            *(uint4*)&g_vth[(size_t)(h * DV + vv) * TT + m0 + tb] = val;
        }
    }
}

// ---------------------------------------------------------------------------
// Kernel E: q (t,h,192) fp32 -> g_qh/g_ql (h,t,192) fp16
// ---------------------------------------------------------------------------
__global__ __launch_bounds__(256) void qsplit_kernel(const float* __restrict__ q) {
    int g = blockIdx.x * 256 + threadIdx.x;   // over elems/8
    int u = g % 24;
    int th = g / 24;
    int h = th & 15;
    int t = th >> 4;
    int d8 = u * 8;
    float4 a = *(const float4*)&q[(size_t)(t * HH + h) * DQK + d8];
    float4 b = *(const float4*)&q[(size_t)(t * HH + h) * DQK + d8 + 4];
    float x[8] = {a.x, a.y, a.z, a.w, b.x, b.y, b.z, b.w};
    uint32_t ph[4], pl[4];
#pragma unroll
    for (int j = 0; j < 4; j++) split2pack(x[2 * j], x[2 * j + 1], ph[j], pl[j]);
    size_t o = (size_t)(h * TT + t) * DQK + d8;
    *(uint4*)&g_qh[o] = make_uint4(ph[0], ph[1], ph[2], ph[3]);
    *(uint4*)&g_ql[o] = make_uint4(pl[0], pl[1], pl[2], pl[3]);
}

// ---------------------------------------------------------------------------
// Kernel F: flash attention on mma.sync (HMMA). q-tile 128, k-tile 64.
// Single-buffer staging (R10 layout). QK = QhKh + QlKh + QhKl; PV = (Ph+Pl)*Vh.
// ---------------------------------------------------------------------------
#define SQH 0
#define SQL 12288
#define SKH 24576
#define SKL 30720
#define SVH 36864
#define FLASH_SMEM_BYTES (40960 * 4)

__global__ __launch_bounds__(256, 1) void flash_mma_kernel(float* __restrict__ out) {
    extern __shared__ uint32_t smw[];
    const int tid = threadIdx.x;
    const int w = tid >> 5, lane = tid & 31;
    const int gr = lane >> 2, tg = lane & 3;
    const int laneSw = SWZ(lane);
    const int id = blockIdx.x;
    const int h = id & 15, qb = 15 - (id >> 4);   // heaviest q-tiles first
    const int t0 = qb * 128;
    const int nsteps = 2 * qb + 2;

    // ---- stage Q fragments (once per CTA) ----
#pragma unroll
    for (int i = 0; i < 12; i++) {
        int idx = tid + i * 256;
        int rr = idx / 24, u24 = idx % 24;
        int ch = u24 >> 1, kk0h = u24 & 1;
        int mt = rr >> 4, r16 = rr & 15;
        int u = r16 & 7;
        int reg = (kk0h << 1) | (r16 >> 3);
        int row = (ch * 8 + mt) * 32, cx = ch & 7;
        int s0_ = row + (SWZ(u * 4 + 0) ^ cx);
        int s1_ = row + (SWZ(u * 4 + 1) ^ cx);
        int s2_ = row + (SWZ(u * 4 + 2) ^ cx);
        int s3_ = row + (SWZ(u * 4 + 3) ^ cx);
        size_t go = (size_t)(h * TT + t0 + rr) * DQK + ch * 16 + kk0h * 8;
        uint4 vh = *(const uint4*)&g_qh[go];
        uint4 vl = *(const uint4*)&g_ql[go];
        smw[SQH + s0_ * 4 + reg] = vh.x;
        smw[SQH + s1_ * 4 + reg] = vh.y;
        smw[SQH + s2_ * 4 + reg] = vh.z;
        smw[SQH + s3_ * 4 + reg] = vh.w;
        smw[SQL + s0_ * 4 + reg] = vl.x;
        smw[SQL + s1_ * 4 + reg] = vl.y;
        smw[SQL + s2_ * 4 + reg] = vl.z;
        smw[SQL + s3_ * 4 + reg] = vl.w;
    }

    float mA = -1.0e30f, mB = -1.0e30f, lA = 0.f, lB = 0.f;
    float O[16][4];
#pragma unroll
    for (int n = 0; n < 16; n++)
#pragma unroll
        for (int e = 0; e < 4; e++) O[n][e] = 0.f;

    for (int sb = 0; sb < nsteps; sb++) {
        const int s0 = sb * 64;
        __syncthreads();

        // ---- stage K hi/lo fragments ----
#pragma unroll
        for (int i = 0; i < 6; i++) {
            int idx = tid + i * 256;
            int sr = idx / 24, u24 = idx % 24;
            int ch = u24 >> 1, kk0h = u24 & 1;
            int nt = sr >> 3, u = sr & 7;
            int reg = kk0h;
            int row = (ch * 8 + nt) * 32, cx = ch & 7;
            int s0_ = row + (SWZ(u * 4 + 0) ^ cx);
            int s1_ = row + (SWZ(u * 4 + 1) ^ cx);
            int s2_ = row + (SWZ(u * 4 + 2) ^ cx);
            int s3_ = row + (SWZ(u * 4 + 3) ^ cx);
            size_t go = (size_t)(h * TT + s0 + sr) * DQK + ch * 16 + kk0h * 8;
            uint4 vh = *(const uint4*)&g_kh[go];
            uint4 vl = *(const uint4*)&g_kl[go];
            smw[SKH + s0_ * 2 + reg] = vh.x;
            smw[SKH + s1_ * 2 + reg] = vh.y;
            smw[SKH + s2_ * 2 + reg] = vh.z;
            smw[SKH + s3_ * 2 + reg] = vh.w;
            smw[SKL + s0_ * 2 + reg] = vl.x;
            smw[SKL + s1_ * 2 + reg] = vl.y;
            smw[SKL + s2_ * 2 + reg] = vl.z;
            smw[SKL + s3_ * 2 + reg] = vl.w;
        }
        // ---- stage V hi fragments ----
#pragma unroll
        for (int i = 0; i < 4; i++) {
            int idx = tid + i * 256;
            int v = idx >> 3, u8 = idx & 7;
            int ch = u8 >> 1, kk0h = u8 & 1;
            int nt = v >> 3, u = v & 7;
            int reg = kk0h;
            int row = (ch * 16 + nt) * 32, cx = ch;
            int s0_ = row + (SWZ(u * 4 + 0) ^ cx);
            int s1_ = row + (SWZ(u * 4 + 1) ^ cx);
            int s2_ = row + (SWZ(u * 4 + 2) ^ cx);
            int s3_ = row + (SWZ(u * 4 + 3) ^ cx);
            size_t go = (size_t)(h * DV + v) * TT + s0 + ch * 16 + kk0h * 8;
            uint4 vv = *(const uint4*)&g_vth[go];
            smw[SVH + s0_ * 2 + reg] = vv.x;
            smw[SVH + s1_ * 2 + reg] = vv.y;
            smw[SVH + s2_ * 2 + reg] = vv.z;
            smw[SVH + s3_ * 2 + reg] = vv.w;
        }
        __syncthreads();

        if (s0 > t0 + w * 16 + 15) continue;   // warp tile fully masked

        // ---- S = Q K^T ----
        float S[8][4];
#pragma unroll
        for (int n = 0; n < 8; n++)
#pragma unroll
            for (int e = 0; e < 4; e++) S[n][e] = 0.f;

#pragma unroll 1
        for (int ch = 0; ch < 12; ch++) {
            int lsw = laneSw ^ (ch & 7);
            uint32_t ab = (uint32_t)(((ch * 8 + w) * 32 + lsw) * 4);
            uint4 aH4 = *(const uint4*)&smw[SQH + ab];
            uint4 aL4 = *(const uint4*)&smw[SQL + ab];
            uint32_t aH[4] = {aH4.x, aH4.y, aH4.z, aH4.w};
            uint32_t aL[4] = {aL4.x, aL4.y, aL4.z, aL4.w};
#pragma unroll
            for (int nt = 0; nt < 8; nt++) {
                uint32_t kb = (uint32_t)(((ch * 8 + nt) * 32 + lsw) * 2);
                uint2 bH = *(const uint2*)&smw[SKH + kb];
                uint32_t bh[2] = {bH.x, bH.y};
                mma16816(S[nt], aH, bh);
                mma16816(S[nt], aL, bh);
                uint2 bL = *(const uint2*)&smw[SKL + kb];
                uint32_t bl[2] = {bL.x, bL.y};
                mma16816(S[nt], aH, bl);
            }
        }

        // ---- scale + causal mask ----
        const int rowA = t0 + w * 16 + gr;
        const bool msk = (s0 + 63 > rowA);
#pragma unroll
        for (int nt = 0; nt < 8; nt++) {
            int col = s0 + nt * 8 + 2 * tg;
#pragma unroll
            for (int e = 0; e < 2; e++) {
                float xA = S[nt][e] * ATT_SCALE;
                float xB = S[nt][2 + e] * ATT_SCALE;
                if (msk) {
                    if (col + e > rowA) xA = -1.0e30f;
                    if (col + e > rowA + 8) xB = -1.0e30f;
                }
                S[nt][e] = xA;
                S[nt][2 + e] = xB;
            }
        }

        // ---- online softmax ----
        float pmA = -1.0e30f, pmB = -1.0e30f;
#pragma unroll
        for (int nt = 0; nt < 8; nt++) {
            pmA = fmaxf(pmA, fmaxf(S[nt][0], S[nt][1]));
            pmB = fmaxf(pmB, fmaxf(S[nt][2], S[nt][3]));
        }
        pmA = fmaxf(pmA, __shfl_xor_sync(0xffffffffu, pmA, 1));
        pmA = fmaxf(pmA, __shfl_xor_sync(0xffffffffu, pmA, 2));
        pmB = fmaxf(pmB, __shfl_xor_sync(0xffffffffu, pmB, 1));
        pmB = fmaxf(pmB, __shfl_xor_sync(0xffffffffu, pmB, 2));
        float mnA = fmaxf(mA, pmA), mnB = fmaxf(mB, pmB);
        float aAf = __expf(mA - mnA), aBf = __expf(mB - mnB);
        float sA = 0.f, sB = 0.f;
#pragma unroll
        for (int nt = 0; nt < 8; nt++) {
            S[nt][0] = __expf(S[nt][0] - mnA);
            S[nt][1] = __expf(S[nt][1] - mnA);
            S[nt][2] = __expf(S[nt][2] - mnB);
            S[nt][3] = __expf(S[nt][3] - mnB);
            sA += S[nt][0] + S[nt][1];
            sB += S[nt][2] + S[nt][3];
        }
        sA += __shfl_xor_sync(0xffffffffu, sA, 1);
        sA += __shfl_xor_sync(0xffffffffu, sA, 2);
        sB += __shfl_xor_sync(0xffffffffu, sB, 1);
        sB += __shfl_xor_sync(0xffffffffu, sB, 2);
        lA = lA * aAf + sA; mA = mnA;
        lB = lB * aBf + sB; mB = mnB;
#pragma unroll
        for (int n = 0; n < 16; n++) {
            O[n][0] *= aAf; O[n][1] *= aAf;
            O[n][2] *= aBf; O[n][3] *= aBf;
        }

        // ---- O += P V ----
#pragma unroll 1
        for (int c = 0; c < 4; c++) {
            uint32_t aPh[4], aPl[4];
#pragma unroll
            for (int q2 = 0; q2 < 2; q2++)
#pragma unroll
                for (int pr = 0; pr < 2; pr++)
                    split2pack(S[2 * c + q2][pr * 2], S[2 * c + q2][pr * 2 + 1],
                               aPh[q2 * 2 + pr], aPl[q2 * 2 + pr]);
            int lswv = laneSw ^ c;
#pragma unroll
            for (int nt = 0; nt < 16; nt++) {
                uint32_t vb = (uint32_t)(((c * 16 + nt) * 32 + lswv) * 2);
                uint2 bV = *(const uint2*)&smw[SVH + vb];
                uint32_t b2[2] = {bV.x, bV.y};
                mma16816(O[nt], aPh, b2);
                mma16816(O[nt], aPl, b2);
            }
        }
    }

    // ---- epilogue ----
    const float iA = 1.f / lA, iB = 1.f / lB;
    const int rowA = t0 + w * 16 + gr;
#pragma unroll
    for (int nt = 0; nt < 16; nt++) {
        int col = h * DV + nt * 8 + 2 * tg;
        *(float2*)&out[(size_t)rowA * (HH * DV) + col] =
            make_float2(O[nt][0] * iA, O[nt][1] * iA);
        *(float2*)&out[(size_t)(rowA + 8) * (HH * DV) + col] =
            make_float2(O[nt][2] * iB, O[nt][3] * iB);
    }
}

// ---------------------------------------------------------------------------
extern "C" void kernel_launch(void* const* d_in, const int* in_sizes, int n_in,
                              void* d_out, int out_size) {
    const float* q   = (const float*)d_in[0];   // (T, H, 192)
    const float* kc  = (const float*)d_in[1];   // (T, 512)
    const float* kpe = (const float*)d_in[2];   // (T, 64)
    const float* wkv = (const float*)d_in[3];   // (512, 4096)
    const float* wuv = (const float*)d_in[4];   // (H, 512, 128)
    float* out = (float*)d_out;                 // (T, 2048)

    kcsplit_kernel<<<TT * DLORA / 8 / 256, 256>>>(kc);
    wkvsplit_kernel<<<dim3(8, 2, 16), 256>>>(wkv);
    wuvsplit_kernel<<<dim3(8, 2, 16), 256>>>(wuv);
    prolog_gemm_kernel<<<dim3(32, 16), 256>>>();
    pefill_kernel<<<(HH * TT * DROPE + 255) / 256, 256>>>(kpe);
    qsplit_kernel<<<HH * TT * DQK / 8 / 256, 256>>>(q);

    cudaFuncSetAttribute(flash_mma_kernel, cudaFuncAttributeMaxDynamicSharedMemorySize,
                         FLASH_SMEM_BYTES);
    flash_mma_kernel<<<256, 256, FLASH_SMEM_BYTES>>>(out);
}

// round 13
// speedup vs baseline: 1.1329x; 1.0701x over previous
#include <cuda_runtime.h>
#include <cuda_fp16.h>
#include <math.h>
#include <stdint.h>

#define TT     2048
#define HH     16
#define DQK    192
#define DNOPE  128
#define DROPE  64
#define DLORA  512
#define DV     128
#define ATT_SCALE 0.07216878364870323f   // 1/sqrt(192)

// ---------------- scratch (static __device__; no cudaMalloc allowed) --------
__device__ __half g_qh[HH * TT * DQK];         // fp16 hi (h,t,192)
__device__ __half g_ql[HH * TT * DQK];         // fp16 lo
__device__ __half g_kh[HH * TT * DQK];
__device__ __half g_kl[HH * TT * DQK];
__device__ __half g_vth[HH * DV * TT];         // fp16 hi V^T (h,v,t)
__device__ __half g_ach[TT * DLORA];           // kc hi (t,k)
__device__ __half g_acl[TT * DLORA];           // kc lo
__device__ __half g_wbh[HH * 256 * DLORA];     // weights hi (n,k), n=h*256+j
__device__ __half g_wbl[HH * 256 * DLORA];     // weights lo

// ---------------------------------------------------------------------------
// helpers
// ---------------------------------------------------------------------------
__device__ __forceinline__ void split2pack(float x, float y, uint32_t& hi, uint32_t& lo) {
    __half hx = __float2half_rn(x), hy = __float2half_rn(y);
    __half lx = __float2half_rn(x - __half2float(hx));
    __half ly = __float2half_rn(y - __half2float(hy));
    hi = (uint32_t)__half_as_ushort(hx) | ((uint32_t)__half_as_ushort(hy) << 16);
    lo = (uint32_t)__half_as_ushort(lx) | ((uint32_t)__half_as_ushort(ly) << 16);
}

__device__ __forceinline__ void mma16816(float* d, const uint32_t* a, const uint32_t* b) {
    asm volatile(
        "mma.sync.aligned.m16n8k16.row.col.f32.f16.f16.f32 "
        "{%0,%1,%2,%3}, {%4,%5,%6,%7}, {%8,%9}, {%0,%1,%2,%3};"
        : "+f"(d[0]), "+f"(d[1]), "+f"(d[2]), "+f"(d[3])
        : "r"(a[0]), "r"(a[1]), "r"(a[2]), "r"(a[3]), "r"(b[0]), "r"(b[1]));
}

// 16B-slot swizzle: conflict-free fragment staging
#define SWZ(s) ((s) ^ (((s) >> 2) & 7))

// ---------------------------------------------------------------------------
// Merged prep kernel: kcsplit | qsplit | wkvsplit | wuvsplit | pefill
// block ranges: [0,512) kc, [512,3584) q, [3584,3840) wkv, [3840,4096) wuv,
//               [4096,6144) pe
// ---------------------------------------------------------------------------
#define NB_KC   512
#define NB_Q    3072
#define NB_WKV  256
#define NB_WUV  256
#define NB_PE   2048
#define NB_TOTAL (NB_KC + NB_Q + NB_WKV + NB_WUV + NB_PE)

__global__ __launch_bounds__(256) void prep_kernel(const float* __restrict__ kc,
                                                   const float* __restrict__ wkv,
                                                   const float* __restrict__ wuv,
                                                   const float* __restrict__ kpe,
                                                   const float* __restrict__ q) {
    __shared__ float ts[64][65];
    const int bid = blockIdx.x;
    const int tid = threadIdx.x;

    if (bid < NB_KC) {
        // ---- kc split ----
        int g = bid * 256 + tid;
        size_t off = (size_t)g * 8;
        float4 a = *(const float4*)&kc[off];
        float4 b = *(const float4*)&kc[off + 4];
        float x[8] = {a.x, a.y, a.z, a.w, b.x, b.y, b.z, b.w};
        uint32_t ph[4], pl[4];
#pragma unroll
        for (int j = 0; j < 4; j++) split2pack(x[2 * j], x[2 * j + 1], ph[j], pl[j]);
        *(uint4*)&g_ach[off] = make_uint4(ph[0], ph[1], ph[2], ph[3]);
        *(uint4*)&g_acl[off] = make_uint4(pl[0], pl[1], pl[2], pl[3]);
    } else if (bid < NB_KC + NB_Q) {
        // ---- q split ----
        int g = (bid - NB_KC) * 256 + tid;
        int u = g % 24;
        int th = g / 24;
        int h = th & 15;
        int t = th >> 4;
        int d8 = u * 8;
        float4 a = *(const float4*)&q[(size_t)(t * HH + h) * DQK + d8];
        float4 b = *(const float4*)&q[(size_t)(t * HH + h) * DQK + d8 + 4];
        float x[8] = {a.x, a.y, a.z, a.w, b.x, b.y, b.z, b.w};
        uint32_t ph[4], pl[4];
#pragma unroll
        for (int j = 0; j < 4; j++) split2pack(x[2 * j], x[2 * j + 1], ph[j], pl[j]);
        size_t o = (size_t)(h * TT + t) * DQK + d8;
        *(uint4*)&g_qh[o] = make_uint4(ph[0], ph[1], ph[2], ph[3]);
        *(uint4*)&g_ql[o] = make_uint4(pl[0], pl[1], pl[2], pl[3]);
    } else if (bid < NB_KC + NB_Q + NB_WKV + NB_WUV) {
        // ---- weight split-transpose (wkv or wuv) ----
        const bool isWkv = (bid < NB_KC + NB_Q + NB_WKV);
        int local = bid - (isWkv ? (NB_KC + NB_Q) : (NB_KC + NB_Q + NB_WKV));
        const int k0 = (local & 7) * 64;
        const int j0 = ((local >> 3) & 1) * 64;
        const int h  = local >> 4;
#pragma unroll
        for (int i = 0; i < 16; i++) {
            int idx = tid + i * 256;
            int kk = idx >> 6, jj = idx & 63;
            ts[kk][jj] = isWkv
                ? wkv[(size_t)(k0 + kk) * (HH * 256) + h * 256 + j0 + jj]
                : wuv[(size_t)(h * DLORA + k0 + kk) * DV + j0 + jj];
        }
        __syncthreads();
        const int nbase = h * 256 + (isWkv ? 0 : 128) + j0;
#pragma unroll
        for (int i = 0; i < 16; i++) {
            int idx = tid + i * 256;
            int jj = idx >> 6, kk = idx & 63;
            float x = ts[kk][jj];
            __half hx = __float2half_rn(x);
            __half lx = __float2half_rn(x - __half2float(hx));
            size_t o = (size_t)(nbase + jj) * DLORA + k0 + kk;
            g_wbh[o] = hx;
            g_wbl[o] = lx;
        }
    } else {
        // ---- pefill (x4 vectorized) ----
        int g = (bid - (NB_KC + NB_Q + NB_WKV + NB_WUV)) * 256 + tid;
        int r4 = g & 15;
        int t = (g >> 4) & (TT - 1);
        int h = g >> 15;
        float4 v = *(const float4*)&kpe[t * DROPE + r4 * 4];
        float x[4] = {v.x, v.y, v.z, v.w};
        uint32_t hi0, lo0, hi1, lo1;
        split2pack(x[0], x[1], hi0, lo0);
        split2pack(x[2], x[3], hi1, lo1);
        size_t o = (size_t)(h * TT + t) * DQK + DNOPE + r4 * 4;
        *(uint2*)&g_kh[o] = make_uint2(hi0, hi1);
        *(uint2*)&g_kl[o] = make_uint2(lo0, lo1);
    }
}

// ---------------------------------------------------------------------------
// Prologue GEMM on HMMA: 128 threads, 4 warps, 64x64 warp tiles.
// C(128m x 128n) = Ahi/lo @ Bhi/lo (K=512), 3 split passes.
// n-tile even -> K_nope (hi/lo split out); odd -> V (hi, transposed).
// ---------------------------------------------------------------------------
#define GA_H 0
#define GA_L 1024
#define GB_H 2048
#define GB_L 3072
#define GEMM_SMEM_BYTES 36864   // max(16KB staging, 128*144*2 V-transpose)

__global__ __launch_bounds__(128) void prolog_gemm_kernel() {
    __shared__ __align__(16) char smbuf[GEMM_SMEM_BYTES];
    uint32_t* smw = (uint32_t*)smbuf;
    const int tid = threadIdx.x;
    const int w = tid >> 5, lane = tid & 31;
    const int gr = lane >> 2, tg = lane & 3;
    const int laneSw = SWZ(lane);
    const int n0 = blockIdx.x * 128;
    const int m0 = blockIdx.y * 128;
    const int h = n0 >> 8;
    const bool isK = ((n0 & 255) == 0);
    const int wm = w >> 1, wn = w & 1;

    float C[4][8][4];
#pragma unroll
    for (int a = 0; a < 4; a++)
#pragma unroll
        for (int b = 0; b < 8; b++)
#pragma unroll
            for (int e = 0; e < 4; e++) C[a][b][e] = 0.f;

    // staging indices: thread stages rows rr and rr+64 of both A and B
    const int rr = tid >> 1, kk0h = tid & 1;
    const int r16 = rr & 15, uA = r16 & 7;
    const int regA = (kk0h << 1) | (r16 >> 3);
    const int baseA = (rr >> 4) * 32;
    const int sA0 = baseA + SWZ(uA * 4 + 0);
    const int sA1 = baseA + SWZ(uA * 4 + 1);
    const int sA2 = baseA + SWZ(uA * 4 + 2);
    const int sA3 = baseA + SWZ(uA * 4 + 3);
    const int uB = rr & 7, regB = kk0h;
    const int baseB = (rr >> 3) * 32;
    const int sB0 = baseB + SWZ(uB * 4 + 0);
    const int sB1 = baseB + SWZ(uB * 4 + 1);
    const int sB2 = baseB + SWZ(uB * 4 + 2);
    const int sB3 = baseB + SWZ(uB * 4 + 3);

    const size_t aoff = (size_t)(m0 + rr) * DLORA + kk0h * 8;
    const size_t boff = (size_t)(n0 + rr) * DLORA + kk0h * 8;
    const size_t rstep = (size_t)64 * DLORA;

    for (int k0 = 0; k0 < DLORA; k0 += 16) {
        // loads issued before the barrier (hidden under previous compute tail)
        uint4 ah0 = *(const uint4*)&g_ach[aoff + k0];
        uint4 ah1 = *(const uint4*)&g_ach[aoff + rstep + k0];
        uint4 al0 = *(const uint4*)&g_acl[aoff + k0];
        uint4 al1 = *(const uint4*)&g_acl[aoff + rstep + k0];
        uint4 bh0 = *(const uint4*)&g_wbh[boff + k0];
        uint4 bh1 = *(const uint4*)&g_wbh[boff + rstep + k0];
        uint4 bl0 = *(const uint4*)&g_wbl[boff + k0];
        uint4 bl1 = *(const uint4*)&g_wbl[boff + rstep + k0];
        __syncthreads();   // previous compute done reading smem

        smw[GA_H + sA0 * 4 + regA] = ah0.x;
        smw[GA_H + sA1 * 4 + regA] = ah0.y;
        smw[GA_H + sA2 * 4 + regA] = ah0.z;
        smw[GA_H + sA3 * 4 + regA] = ah0.w;
        smw[GA_H + (sA0 + 128) * 4 + regA] = ah1.x;
        smw[GA_H + (sA1 + 128) * 4 + regA] = ah1.y;
        smw[GA_H + (sA2 + 128) * 4 + regA] = ah1.z;
        smw[GA_H + (sA3 + 128) * 4 + regA] = ah1.w;
        smw[GA_L + sA0 * 4 + regA] = al0.x;
        smw[GA_L + sA1 * 4 + regA] = al0.y;
        smw[GA_L + sA2 * 4 + regA] = al0.z;
        smw[GA_L + sA3 * 4 + regA] = al0.w;
        smw[GA_L + (sA0 + 128) * 4 + regA] = al1.x;
        smw[GA_L + (sA1 + 128) * 4 + regA] = al1.y;
        smw[GA_L + (sA2 + 128) * 4 + regA] = al1.z;
        smw[GA_L + (sA3 + 128) * 4 + regA] = al1.w;
        smw[GB_H + sB0 * 2 + regB] = bh0.x;
        smw[GB_H + sB1 * 2 + regB] = bh0.y;
        smw[GB_H + sB2 * 2 + regB] = bh0.z;
        smw[GB_H + sB3 * 2 + regB] = bh0.w;
        smw[GB_H + (sB0 + 256) * 2 + regB] = bh1.x;
        smw[GB_H + (sB1 + 256) * 2 + regB] = bh1.y;
        smw[GB_H + (sB2 + 256) * 2 + regB] = bh1.z;
        smw[GB_H + (sB3 + 256) * 2 + regB] = bh1.w;
        smw[GB_L + sB0 * 2 + regB] = bl0.x;
        smw[GB_L + sB1 * 2 + regB] = bl0.y;
        smw[GB_L + sB2 * 2 + regB] = bl0.z;
        smw[GB_L + sB3 * 2 + regB] = bl0.w;
        smw[GB_L + (sB0 + 256) * 2 + regB] = bl1.x;
        smw[GB_L + (sB1 + 256) * 2 + regB] = bl1.y;
        smw[GB_L + (sB2 + 256) * 2 + regB] = bl1.z;
        smw[GB_L + (sB3 + 256) * 2 + regB] = bl1.w;
        __syncthreads();

        // B fragments once per warp (n-range wn*64 .. +63)
        uint32_t fBH[8][2], fBL[8][2];
#pragma unroll
        for (int n2 = 0; n2 < 8; n2++) {
            uint2 t1 = *(const uint2*)&smw[GB_H + ((wn * 8 + n2) * 32 + laneSw) * 2];
            uint2 t2 = *(const uint2*)&smw[GB_L + ((wn * 8 + n2) * 32 + laneSw) * 2];
            fBH[n2][0] = t1.x; fBH[n2][1] = t1.y;
            fBL[n2][0] = t2.x; fBL[n2][1] = t2.y;
        }

#pragma unroll
        for (int m2 = 0; m2 < 4; m2++) {
            uint4 aH4 = *(const uint4*)&smw[GA_H + ((wm * 4 + m2) * 32 + laneSw) * 4];
            uint4 aL4 = *(const uint4*)&smw[GA_L + ((wm * 4 + m2) * 32 + laneSw) * 4];
            uint32_t aH[4] = {aH4.x, aH4.y, aH4.z, aH4.w};
            uint32_t aL[4] = {aL4.x, aL4.y, aL4.z, aL4.w};
#pragma unroll
            for (int n2 = 0; n2 < 8; n2++) {
                mma16816(C[m2][n2], aH, fBH[n2]);
                mma16816(C[m2][n2], aL, fBH[n2]);
                mma16816(C[m2][n2], aH, fBL[n2]);
            }
        }
    }

    __syncthreads();
    if (isK) {
#pragma unroll
        for (int m2 = 0; m2 < 4; m2++) {
            int row = m0 + wm * 64 + m2 * 16 + gr;
#pragma unroll
            for (int n2 = 0; n2 < 8; n2++) {
                int d = wn * 64 + n2 * 8 + 2 * tg;
                uint32_t hi, lo;
                split2pack(C[m2][n2][0], C[m2][n2][1], hi, lo);
                *(uint32_t*)&g_kh[(size_t)(h * TT + row) * DQK + d] = hi;
                *(uint32_t*)&g_kl[(size_t)(h * TT + row) * DQK + d] = lo;
                split2pack(C[m2][n2][2], C[m2][n2][3], hi, lo);
                *(uint32_t*)&g_kh[(size_t)(h * TT + row + 8) * DQK + d] = hi;
                *(uint32_t*)&g_kl[(size_t)(h * TT + row + 8) * DQK + d] = lo;
            }
        }
    } else {
        __half* sC = (__half*)smbuf;   // [128 v][144]
#pragma unroll
        for (int m2 = 0; m2 < 4; m2++) {
            int t = wm * 64 + m2 * 16 + gr;
#pragma unroll
            for (int n2 = 0; n2 < 8; n2++) {
                int v = wn * 64 + n2 * 8 + 2 * tg;
                sC[v * 144 + t]           = __float2half_rn(C[m2][n2][0]);
                sC[(v + 1) * 144 + t]     = __float2half_rn(C[m2][n2][1]);
                sC[v * 144 + t + 8]       = __float2half_rn(C[m2][n2][2]);
                sC[(v + 1) * 144 + t + 8] = __float2half_rn(C[m2][n2][3]);
            }
        }
        __syncthreads();
#pragma unroll
        for (int i = 0; i < 16; i++) {
            int idx = tid + i * 128;
            int vv = idx >> 4, tb = (idx & 15) * 8;
            uint4 val = *(const uint4*)&sC[vv * 144 + tb];
            *(uint4*)&g_vth[(size_t)(h * DV + vv) * TT + m0 + tb] = val;
        }
    }
}

// ---------------------------------------------------------------------------
// Flash attention on mma.sync (HMMA). q-tile 128, k-tile 64. (R12 verbatim)
// ---------------------------------------------------------------------------
#define SQH 0
#define SQL 12288
#define SKH 24576
#define SKL 30720
#define SVH 36864
#define FLASH_SMEM_BYTES (40960 * 4)

__global__ __launch_bounds__(256, 1) void flash_mma_kernel(float* __restrict__ out) {
    extern __shared__ uint32_t smw[];
    const int tid = threadIdx.x;
    const int w = tid >> 5, lane = tid & 31;
    const int gr = lane >> 2, tg = lane & 3;
    const int laneSw = SWZ(lane);
    const int id = blockIdx.x;
    const int h = id & 15, qb = 15 - (id >> 4);   // heaviest q-tiles first
    const int t0 = qb * 128;
    const int nsteps = 2 * qb + 2;

    // ---- stage Q fragments (once per CTA) ----
#pragma unroll
    for (int i = 0; i < 12; i++) {
        int idx = tid + i * 256;
        int rr = idx / 24, u24 = idx % 24;
        int ch = u24 >> 1, kk0h = u24 & 1;
        int mt = rr >> 4, r16 = rr & 15;
        int u = r16 & 7;
        int reg = (kk0h << 1) | (r16 >> 3);
        int row = (ch * 8 + mt) * 32, cx = ch & 7;
        int s0_ = row + (SWZ(u * 4 + 0) ^ cx);
        int s1_ = row + (SWZ(u * 4 + 1) ^ cx);
        int s2_ = row + (SWZ(u * 4 + 2) ^ cx);
        int s3_ = row + (SWZ(u * 4 + 3) ^ cx);
        size_t go = (size_t)(h * TT + t0 + rr) * DQK + ch * 16 + kk0h * 8;
        uint4 vh = *(const uint4*)&g_qh[go];
        uint4 vl = *(const uint4*)&g_ql[go];
        smw[SQH + s0_ * 4 + reg] = vh.x;
        smw[SQH + s1_ * 4 + reg] = vh.y;
        smw[SQH + s2_ * 4 + reg] = vh.z;
        smw[SQH + s3_ * 4 + reg] = vh.w;
        smw[SQL + s0_ * 4 + reg] = vl.x;
        smw[SQL + s1_ * 4 + reg] = vl.y;
        smw[SQL + s2_ * 4 + reg] = vl.z;
        smw[SQL + s3_ * 4 + reg] = vl.w;
    }

    float mA = -1.0e30f, mB = -1.0e30f, lA = 0.f, lB = 0.f;
    float O[16][4];
#pragma unroll
    for (int n = 0; n < 16; n++)
#pragma unroll
        for (int e = 0; e < 4; e++) O[n][e] = 0.f;

    for (int sb = 0; sb < nsteps; sb++) {
        const int s0 = sb * 64;
        __syncthreads();

        // ---- stage K hi/lo fragments ----
#pragma unroll
        for (int i = 0; i < 6; i++) {
            int idx = tid + i * 256;
            int sr = idx / 24, u24 = idx % 24;
            int ch = u24 >> 1, kk0h = u24 & 1;
            int nt = sr >> 3, u = sr & 7;
            int reg = kk0h;
            int row = (ch * 8 + nt) * 32, cx = ch & 7;
            int s0_ = row + (SWZ(u * 4 + 0) ^ cx);
            int s1_ = row + (SWZ(u * 4 + 1) ^ cx);
            int s2_ = row + (SWZ(u * 4 + 2) ^ cx);
            int s3_ = row + (SWZ(u * 4 + 3) ^ cx);
            size_t go = (size_t)(h * TT + s0 + sr) * DQK + ch * 16 + kk0h * 8;
            uint4 vh = *(const uint4*)&g_kh[go];
            uint4 vl = *(const uint4*)&g_kl[go];
            smw[SKH + s0_ * 2 + reg] = vh.x;
            smw[SKH + s1_ * 2 + reg] = vh.y;
            smw[SKH + s2_ * 2 + reg] = vh.z;
            smw[SKH + s3_ * 2 + reg] = vh.w;
            smw[SKL + s0_ * 2 + reg] = vl.x;
            smw[SKL + s1_ * 2 + reg] = vl.y;
            smw[SKL + s2_ * 2 + reg] = vl.z;
            smw[SKL + s3_ * 2 + reg] = vl.w;
        }
        // ---- stage V hi fragments ----
#pragma unroll
        for (int i = 0; i < 4; i++) {
            int idx = tid + i * 256;
            int v = idx >> 3, u8 = idx & 7;
            int ch = u8 >> 1, kk0h = u8 & 1;
            int nt = v >> 3, u = v & 7;
            int reg = kk0h;
            int row = (ch * 16 + nt) * 32, cx = ch;
            int s0_ = row + (SWZ(u * 4 + 0) ^ cx);
            int s1_ = row + (SWZ(u * 4 + 1) ^ cx);
            int s2_ = row + (SWZ(u * 4 + 2) ^ cx);
            int s3_ = row + (SWZ(u * 4 + 3) ^ cx);
            size_t go = (size_t)(h * DV + v) * TT + s0 + ch * 16 + kk0h * 8;
            uint4 vv = *(const uint4*)&g_vth[go];
            smw[SVH + s0_ * 2 + reg] = vv.x;
            smw[SVH + s1_ * 2 + reg] = vv.y;
            smw[SVH + s2_ * 2 + reg] = vv.z;
            smw[SVH + s3_ * 2 + reg] = vv.w;
        }
        __syncthreads();

        if (s0 > t0 + w * 16 + 15) continue;   // warp tile fully masked

        // ---- S = Q K^T ----
        float S[8][4];
#pragma unroll
        for (int n = 0; n < 8; n++)
#pragma unroll
            for (int e = 0; e < 4; e++) S[n][e] = 0.f;

#pragma unroll 1
        for (int ch = 0; ch < 12; ch++) {
            int lsw = laneSw ^ (ch & 7);
            uint32_t ab = (uint32_t)(((ch * 8 + w) * 32 + lsw) * 4);
            uint4 aH4 = *(const uint4*)&smw[SQH + ab];
            uint4 aL4 = *(const uint4*)&smw[SQL + ab];
            uint32_t aH[4] = {aH4.x, aH4.y, aH4.z, aH4.w};
            uint32_t aL[4] = {aL4.x, aL4.y, aL4.z, aL4.w};
#pragma unroll
            for (int nt = 0; nt < 8; nt++) {
                uint32_t kb = (uint32_t)(((ch * 8 + nt) * 32 + lsw) * 2);
                uint2 bH = *(const uint2*)&smw[SKH + kb];
                uint32_t bh[2] = {bH.x, bH.y};
                mma16816(S[nt], aH, bh);
                mma16816(S[nt], aL, bh);
                uint2 bL = *(const uint2*)&smw[SKL + kb];
                uint32_t bl[2] = {bL.x, bL.y};
                mma16816(S[nt], aH, bl);
            }
        }

        // ---- scale + causal mask ----
        const int rowA = t0 + w * 16 + gr;
        const bool msk = (s0 + 63 > rowA);
#pragma unroll
        for (int nt = 0; nt < 8; nt++) {
            int col = s0 + nt * 8 + 2 * tg;
#pragma unroll
            for (int e = 0; e < 2; e++) {
                float xA = S[nt][e] * ATT_SCALE;
                float xB = S[nt][2 + e] * ATT_SCALE;
                if (msk) {
                    if (col + e > rowA) xA = -1.0e30f;
                    if (col + e > rowA + 8) xB = -1.0e30f;
                }
                S[nt][e] = xA;
                S[nt][2 + e] = xB;
            }
        }

        // ---- online softmax ----
        float pmA = -1.0e30f, pmB = -1.0e30f;
#pragma unroll
        for (int nt = 0; nt < 8; nt++) {
            pmA = fmaxf(pmA, fmaxf(S[nt][0], S[nt][1]));
            pmB = fmaxf(pmB, fmaxf(S[nt][2], S[nt][3]));
        }
        pmA = fmaxf(pmA, __shfl_xor_sync(0xffffffffu, pmA, 1));
        pmA = fmaxf(pmA, __shfl_xor_sync(0xffffffffu, pmA, 2));
        pmB = fmaxf(pmB, __shfl_xor_sync(0xffffffffu, pmB, 1));
        pmB = fmaxf(pmB, __shfl_xor_sync(0xffffffffu, pmB, 2));
        float mnA = fmaxf(mA, pmA), mnB = fmaxf(mB, pmB);
        float aAf = __expf(mA - mnA), aBf = __expf(mB - mnB);
        float sA = 0.f, sB = 0.f;
#pragma unroll
        for (int nt = 0; nt < 8; nt++) {
            S[nt][0] = __expf(S[nt][0] - mnA);
            S[nt][1] = __expf(S[nt][1] - mnA);
            S[nt][2] = __expf(S[nt][2] - mnB);
            S[nt][3] = __expf(S[nt][3] - mnB);
            sA += S[nt][0] + S[nt][1];
            sB += S[nt][2] + S[nt][3];
        }
        sA += __shfl_xor_sync(0xffffffffu, sA, 1);
        sA += __shfl_xor_sync(0xffffffffu, sA, 2);
        sB += __shfl_xor_sync(0xffffffffu, sB, 1);
        sB += __shfl_xor_sync(0xffffffffu, sB, 2);
        lA = lA * aAf + sA; mA = mnA;
        lB = lB * aBf + sB; mB = mnB;
#pragma unroll
        for (int n = 0; n < 16; n++) {
            O[n][0] *= aAf; O[n][1] *= aAf;
            O[n][2] *= aBf; O[n][3] *= aBf;
        }

        // ---- O += P V ----
#pragma unroll 1
        for (int c = 0; c < 4; c++) {
            uint32_t aPh[4], aPl[4];
#pragma unroll
            for (int q2 = 0; q2 < 2; q2++)
#pragma unroll
                for (int pr = 0; pr < 2; pr++)
                    split2pack(S[2 * c + q2][pr * 2], S[2 * c + q2][pr * 2 + 1],
                               aPh[q2 * 2 + pr], aPl[q2 * 2 + pr]);
            int lswv = laneSw ^ c;
#pragma unroll
            for (int nt = 0; nt < 16; nt++) {
                uint32_t vb = (uint32_t)(((c * 16 + nt) * 32 + lswv) * 2);
                uint2 bV = *(const uint2*)&smw[SVH + vb];
                uint32_t b2[2] = {bV.x, bV.y};
                mma16816(O[nt], aPh, b2);
                mma16816(O[nt], aPl, b2);
            }
        }
    }

    // ---- epilogue ----
    const float iA = 1.f / lA, iB = 1.f / lB;
    const int rowA = t0 + w * 16 + gr;
#pragma unroll
    for (int nt = 0; nt < 16; nt++) {
        int col = h * DV + nt * 8 + 2 * tg;
        *(float2*)&out[(size_t)rowA * (HH * DV) + col] =
            make_float2(O[nt][0] * iA, O[nt][1] * iA);
        *(float2*)&out[(size_t)(rowA + 8) * (HH * DV) + col] =
            make_float2(O[nt][2] * iB, O[nt][3] * iB);
    }
}

// ---------------------------------------------------------------------------
extern "C" void kernel_launch(void* const* d_in, const int* in_sizes, int n_in,
                              void* d_out, int out_size) {
    const float* q   = (const float*)d_in[0];   // (T, H, 192)
    const float* kc  = (const float*)d_in[1];   // (T, 512)
    const float* kpe = (const float*)d_in[2];   // (T, 64)
    const float* wkv = (const float*)d_in[3];   // (512, 4096)
    const float* wuv = (const float*)d_in[4];   // (H, 512, 128)
    float* out = (float*)d_out;                 // (T, 2048)

    prep_kernel<<<NB_TOTAL, 256>>>(kc, wkv, wuv, kpe, q);
    prolog_gemm_kernel<<<dim3(32, 16), 128>>>();

    cudaFuncSetAttribute(flash_mma_kernel, cudaFuncAttributeMaxDynamicSharedMemorySize,
                         FLASH_SMEM_BYTES);
    flash_mma_kernel<<<256, 256, FLASH_SMEM_BYTES>>>(out);
}

// round 14
// speedup vs baseline: 1.2938x; 1.1421x over previous
#include <cuda_runtime.h>
#include <cuda_fp16.h>
#include <math.h>
#include <stdint.h>

#define TT     2048
#define HH     16
#define DQK    192
#define DNOPE  128
#define DROPE  64
#define DLORA  512
#define DV     128
#define ATT_SCALE 0.07216878364870323f   // 1/sqrt(192)

// ---------------- scratch (static __device__; no cudaMalloc allowed) --------
__device__ __half g_qh[HH * TT * DQK];         // fp16 hi (h,t,192)
__device__ __half g_ql[HH * TT * DQK];         // fp16 lo
__device__ __half g_kh[HH * TT * DQK];         // K: hi only (lo term dropped)
__device__ __half g_vth[HH * DV * TT];         // fp16 hi V^T (h,v,t)
__device__ __half g_ach[TT * DLORA];           // kc hi (t,k)
__device__ __half g_acl[TT * DLORA];           // kc lo
__device__ __half g_wbh[HH * 256 * DLORA];     // weights hi (n,k), n=h*256+j
__device__ __half g_wbl[HH * 256 * DLORA];     // weights lo

// ---------------------------------------------------------------------------
// helpers
// ---------------------------------------------------------------------------
__device__ __forceinline__ void split2pack(float x, float y, uint32_t& hi, uint32_t& lo) {
    __half hx = __float2half_rn(x), hy = __float2half_rn(y);
    __half lx = __float2half_rn(x - __half2float(hx));
    __half ly = __float2half_rn(y - __half2float(hy));
    hi = (uint32_t)__half_as_ushort(hx) | ((uint32_t)__half_as_ushort(hy) << 16);
    lo = (uint32_t)__half_as_ushort(lx) | ((uint32_t)__half_as_ushort(ly) << 16);
}

__device__ __forceinline__ uint32_t pack2h(float x, float y) {
    __half hx = __float2half_rn(x), hy = __float2half_rn(y);
    return (uint32_t)__half_as_ushort(hx) | ((uint32_t)__half_as_ushort(hy) << 16);
}

__device__ __forceinline__ void mma16816(float* d, const uint32_t* a, const uint32_t* b) {
    asm volatile(
        "mma.sync.aligned.m16n8k16.row.col.f32.f16.f16.f32 "
        "{%0,%1,%2,%3}, {%4,%5,%6,%7}, {%8,%9}, {%0,%1,%2,%3};"
        : "+f"(d[0]), "+f"(d[1]), "+f"(d[2]), "+f"(d[3])
        : "r"(a[0]), "r"(a[1]), "r"(a[2]), "r"(a[3]), "r"(b[0]), "r"(b[1]));
}

// 16B-slot swizzle: conflict-free fragment staging
#define SWZ(s) ((s) ^ (((s) >> 2) & 7))

// ---------------------------------------------------------------------------
// Merged prep kernel: kcsplit | qsplit | wkvsplit | wuvsplit | pefill
// ---------------------------------------------------------------------------
#define NB_KC   512
#define NB_Q    3072
#define NB_WKV  256
#define NB_WUV  256
#define NB_PE   2048
#define NB_TOTAL (NB_KC + NB_Q + NB_WKV + NB_WUV + NB_PE)

__global__ __launch_bounds__(256) void prep_kernel(const float* __restrict__ kc,
                                                   const float* __restrict__ wkv,
                                                   const float* __restrict__ wuv,
                                                   const float* __restrict__ kpe,
                                                   const float* __restrict__ q) {
    __shared__ float ts[64][65];
    const int bid = blockIdx.x;
    const int tid = threadIdx.x;

    if (bid < NB_KC) {
        // ---- kc split ----
        int g = bid * 256 + tid;
        size_t off = (size_t)g * 8;
        float4 a = *(const float4*)&kc[off];
        float4 b = *(const float4*)&kc[off + 4];
        float x[8] = {a.x, a.y, a.z, a.w, b.x, b.y, b.z, b.w};
        uint32_t ph[4], pl[4];
#pragma unroll
        for (int j = 0; j < 4; j++) split2pack(x[2 * j], x[2 * j + 1], ph[j], pl[j]);
        *(uint4*)&g_ach[off] = make_uint4(ph[0], ph[1], ph[2], ph[3]);
        *(uint4*)&g_acl[off] = make_uint4(pl[0], pl[1], pl[2], pl[3]);
    } else if (bid < NB_KC + NB_Q) {
        // ---- q split ----
        int g = (bid - NB_KC) * 256 + tid;
        int u = g % 24;
        int th = g / 24;
        int h = th & 15;
        int t = th >> 4;
        int d8 = u * 8;
        float4 a = *(const float4*)&q[(size_t)(t * HH + h) * DQK + d8];
        float4 b = *(const float4*)&q[(size_t)(t * HH + h) * DQK + d8 + 4];
        float x[8] = {a.x, a.y, a.z, a.w, b.x, b.y, b.z, b.w};
        uint32_t ph[4], pl[4];
#pragma unroll
        for (int j = 0; j < 4; j++) split2pack(x[2 * j], x[2 * j + 1], ph[j], pl[j]);
        size_t o = (size_t)(h * TT + t) * DQK + d8;
        *(uint4*)&g_qh[o] = make_uint4(ph[0], ph[1], ph[2], ph[3]);
        *(uint4*)&g_ql[o] = make_uint4(pl[0], pl[1], pl[2], pl[3]);
    } else if (bid < NB_KC + NB_Q + NB_WKV + NB_WUV) {
        // ---- weight split-transpose (wkv or wuv) ----
        const bool isWkv = (bid < NB_KC + NB_Q + NB_WKV);
        int local = bid - (isWkv ? (NB_KC + NB_Q) : (NB_KC + NB_Q + NB_WKV));
        const int k0 = (local & 7) * 64;
        const int j0 = ((local >> 3) & 1) * 64;
        const int h  = local >> 4;
#pragma unroll
        for (int i = 0; i < 16; i++) {
            int idx = tid + i * 256;
            int kk = idx >> 6, jj = idx & 63;
            ts[kk][jj] = isWkv
                ? wkv[(size_t)(k0 + kk) * (HH * 256) + h * 256 + j0 + jj]
                : wuv[(size_t)(h * DLORA + k0 + kk) * DV + j0 + jj];
        }
        __syncthreads();
        const int nbase = h * 256 + (isWkv ? 0 : 128) + j0;
#pragma unroll
        for (int i = 0; i < 16; i++) {
            int idx = tid + i * 256;
            int jj = idx >> 6, kk = idx & 63;
            float x = ts[kk][jj];
            __half hx = __float2half_rn(x);
            __half lx = __float2half_rn(x - __half2float(hx));
            size_t o = (size_t)(nbase + jj) * DLORA + k0 + kk;
            g_wbh[o] = hx;
            g_wbl[o] = lx;
        }
    } else {
        // ---- pefill (x4 vectorized, hi only) ----
        int g = (bid - (NB_KC + NB_Q + NB_WKV + NB_WUV)) * 256 + tid;
        int r4 = g & 15;
        int t = (g >> 4) & (TT - 1);
        int h = g >> 15;
        float4 v = *(const float4*)&kpe[t * DROPE + r4 * 4];
        uint32_t hi0 = pack2h(v.x, v.y);
        uint32_t hi1 = pack2h(v.z, v.w);
        size_t o = (size_t)(h * TT + t) * DQK + DNOPE + r4 * 4;
        *(uint2*)&g_kh[o] = make_uint2(hi0, hi1);
    }
}

// ---------------------------------------------------------------------------
// Prologue GEMM on HMMA: 128 threads, 4 warps, 64x64 warp tiles.
// C(128m x 128n) = Ahi/lo @ Bhi/lo (K=512), 3 split passes.
// n-tile even -> K_nope (hi only); odd -> V (hi, transposed).
// ---------------------------------------------------------------------------
#define GA_H 0
#define GA_L 1024
#define GB_H 2048
#define GB_L 3072
#define GEMM_SMEM_BYTES 36864   // max(16KB staging, 128*144*2 V-transpose)

__global__ __launch_bounds__(128) void prolog_gemm_kernel() {
    __shared__ __align__(16) char smbuf[GEMM_SMEM_BYTES];
    uint32_t* smw = (uint32_t*)smbuf;
    const int tid = threadIdx.x;
    const int w = tid >> 5, lane = tid & 31;
    const int gr = lane >> 2, tg = lane & 3;
    const int laneSw = SWZ(lane);
    const int n0 = blockIdx.x * 128;
    const int m0 = blockIdx.y * 128;
    const int h = n0 >> 8;
    const bool isK = ((n0 & 255) == 0);
    const int wm = w >> 1, wn = w & 1;

    float C[4][8][4];
#pragma unroll
    for (int a = 0; a < 4; a++)
#pragma unroll
        for (int b = 0; b < 8; b++)
#pragma unroll
            for (int e = 0; e < 4; e++) C[a][b][e] = 0.f;

    const int rr = tid >> 1, kk0h = tid & 1;
    const int r16 = rr & 15, uA = r16 & 7;
    const int regA = (kk0h << 1) | (r16 >> 3);
    const int baseA = (rr >> 4) * 32;
    const int sA0 = baseA + SWZ(uA * 4 + 0);
    const int sA1 = baseA + SWZ(uA * 4 + 1);
    const int sA2 = baseA + SWZ(uA * 4 + 2);
    const int sA3 = baseA + SWZ(uA * 4 + 3);
    const int uB = rr & 7, regB = kk0h;
    const int baseB = (rr >> 3) * 32;
    const int sB0 = baseB + SWZ(uB * 4 + 0);
    const int sB1 = baseB + SWZ(uB * 4 + 1);
    const int sB2 = baseB + SWZ(uB * 4 + 2);
    const int sB3 = baseB + SWZ(uB * 4 + 3);

    const size_t aoff = (size_t)(m0 + rr) * DLORA + kk0h * 8;
    const size_t boff = (size_t)(n0 + rr) * DLORA + kk0h * 8;
    const size_t rstep = (size_t)64 * DLORA;

    for (int k0 = 0; k0 < DLORA; k0 += 16) {
        uint4 ah0 = *(const uint4*)&g_ach[aoff + k0];
        uint4 ah1 = *(const uint4*)&g_ach[aoff + rstep + k0];
        uint4 al0 = *(const uint4*)&g_acl[aoff + k0];
        uint4 al1 = *(const uint4*)&g_acl[aoff + rstep + k0];
        uint4 bh0 = *(const uint4*)&g_wbh[boff + k0];
        uint4 bh1 = *(const uint4*)&g_wbh[boff + rstep + k0];
        uint4 bl0 = *(const uint4*)&g_wbl[boff + k0];
        uint4 bl1 = *(const uint4*)&g_wbl[boff + rstep + k0];
        __syncthreads();   // previous compute done reading smem

        smw[GA_H + sA0 * 4 + regA] = ah0.x;
        smw[GA_H + sA1 * 4 + regA] = ah0.y;
        smw[GA_H + sA2 * 4 + regA] = ah0.z;
        smw[GA_H + sA3 * 4 + regA] = ah0.w;
        smw[GA_H + (sA0 + 128) * 4 + regA] = ah1.x;
        smw[GA_H + (sA1 + 128) * 4 + regA] = ah1.y;
        smw[GA_H + (sA2 + 128) * 4 + regA] = ah1.z;
        smw[GA_H + (sA3 + 128) * 4 + regA] = ah1.w;
        smw[GA_L + sA0 * 4 + regA] = al0.x;
        smw[GA_L + sA1 * 4 + regA] = al0.y;
        smw[GA_L + sA2 * 4 + regA] = al0.z;
        smw[GA_L + sA3 * 4 + regA] = al0.w;
        smw[GA_L + (sA0 + 128) * 4 + regA] = al1.x;
        smw[GA_L + (sA1 + 128) * 4 + regA] = al1.y;
        smw[GA_L + (sA2 + 128) * 4 + regA] = al1.z;
        smw[GA_L + (sA3 + 128) * 4 + regA] = al1.w;
        smw[GB_H + sB0 * 2 + regB] = bh0.x;
        smw[GB_H + sB1 * 2 + regB] = bh0.y;
        smw[GB_H + sB2 * 2 + regB] = bh0.z;
        smw[GB_H + sB3 * 2 + regB] = bh0.w;
        smw[GB_H + (sB0 + 256) * 2 + regB] = bh1.x;
        smw[GB_H + (sB1 + 256) * 2 + regB] = bh1.y;
        smw[GB_H + (sB2 + 256) * 2 + regB] = bh1.z;
        smw[GB_H + (sB3 + 256) * 2 + regB] = bh1.w;
        smw[GB_L + sB0 * 2 + regB] = bl0.x;
        smw[GB_L + sB1 * 2 + regB] = bl0.y;
        smw[GB_L + sB2 * 2 + regB] = bl0.z;
        smw[GB_L + sB3 * 2 + regB] = bl0.w;
        smw[GB_L + (sB0 + 256) * 2 + regB] = bl1.x;
        smw[GB_L + (sB1 + 256) * 2 + regB] = bl1.y;
        smw[GB_L + (sB2 + 256) * 2 + regB] = bl1.z;
        smw[GB_L + (sB3 + 256) * 2 + regB] = bl1.w;
        __syncthreads();

        uint32_t fBH[8][2], fBL[8][2];
#pragma unroll
        for (int n2 = 0; n2 < 8; n2++) {
            uint2 t1 = *(const uint2*)&smw[GB_H + ((wn * 8 + n2) * 32 + laneSw) * 2];
            uint2 t2 = *(const uint2*)&smw[GB_L + ((wn * 8 + n2) * 32 + laneSw) * 2];
            fBH[n2][0] = t1.x; fBH[n2][1] = t1.y;
            fBL[n2][0] = t2.x; fBL[n2][1] = t2.y;
        }

#pragma unroll
        for (int m2 = 0; m2 < 4; m2++) {
            uint4 aH4 = *(const uint4*)&smw[GA_H + ((wm * 4 + m2) * 32 + laneSw) * 4];
            uint4 aL4 = *(const uint4*)&smw[GA_L + ((wm * 4 + m2) * 32 + laneSw) * 4];
            uint32_t aH[4] = {aH4.x, aH4.y, aH4.z, aH4.w};
            uint32_t aL[4] = {aL4.x, aL4.y, aL4.z, aL4.w};
#pragma unroll
            for (int n2 = 0; n2 < 8; n2++) {
                mma16816(C[m2][n2], aH, fBH[n2]);
                mma16816(C[m2][n2], aL, fBH[n2]);
                mma16816(C[m2][n2], aH, fBL[n2]);
            }
        }
    }

    __syncthreads();
    if (isK) {
        // K_nope: hi only
#pragma unroll
        for (int m2 = 0; m2 < 4; m2++) {
            int row = m0 + wm * 64 + m2 * 16 + gr;
#pragma unroll
            for (int n2 = 0; n2 < 8; n2++) {
                int d = wn * 64 + n2 * 8 + 2 * tg;
                *(uint32_t*)&g_kh[(size_t)(h * TT + row) * DQK + d] =
                    pack2h(C[m2][n2][0], C[m2][n2][1]);
                *(uint32_t*)&g_kh[(size_t)(h * TT + row + 8) * DQK + d] =
                    pack2h(C[m2][n2][2], C[m2][n2][3]);
            }
        }
    } else {
        __half* sC = (__half*)smbuf;   // [128 v][144]
#pragma unroll
        for (int m2 = 0; m2 < 4; m2++) {
            int t = wm * 64 + m2 * 16 + gr;
#pragma unroll
            for (int n2 = 0; n2 < 8; n2++) {
                int v = wn * 64 + n2 * 8 + 2 * tg;
                sC[v * 144 + t]           = __float2half_rn(C[m2][n2][0]);
                sC[(v + 1) * 144 + t]     = __float2half_rn(C[m2][n2][1]);
                sC[v * 144 + t + 8]       = __float2half_rn(C[m2][n2][2]);
                sC[(v + 1) * 144 + t + 8] = __float2half_rn(C[m2][n2][3]);
            }
        }
        __syncthreads();
#pragma unroll
        for (int i = 0; i < 16; i++) {
            int idx = tid + i * 128;
            int vv = idx >> 4, tb = (idx & 15) * 8;
            uint4 val = *(const uint4*)&sC[vv * 144 + tb];
            *(uint4*)&g_vth[(size_t)(h * DV + vv) * TT + m0 + tb] = val;
        }
    }
}

// ---------------------------------------------------------------------------
// Flash attention on mma.sync (HMMA). q-tile 128, k-tile 64.
// QK = QhKh + QlKh (Kl dropped); PV = (Ph + Pl) * Vh.
// ---------------------------------------------------------------------------
#define SQH 0
#define SQL 12288
#define SKH 24576
#define SVH 30720
#define FLASH_SMEM_BYTES ((30720 + 4096) * 4)

__global__ __launch_bounds__(256, 1) void flash_mma_kernel(float* __restrict__ out) {
    extern __shared__ uint32_t smw[];
    const int tid = threadIdx.x;
    const int w = tid >> 5, lane = tid & 31;
    const int gr = lane >> 2, tg = lane & 3;
    const int laneSw = SWZ(lane);
    const int id = blockIdx.x;
    const int h = id & 15, qb = 15 - (id >> 4);   // heaviest q-tiles first
    const int t0 = qb * 128;
    const int nsteps = 2 * qb + 2;

    // ---- stage Q fragments (once per CTA) ----
#pragma unroll
    for (int i = 0; i < 12; i++) {
        int idx = tid + i * 256;
        int rr = idx / 24, u24 = idx % 24;
        int ch = u24 >> 1, kk0h = u24 & 1;
        int mt = rr >> 4, r16 = rr & 15;
        int u = r16 & 7;
        int reg = (kk0h << 1) | (r16 >> 3);
        int row = (ch * 8 + mt) * 32, cx = ch & 7;
        int s0_ = row + (SWZ(u * 4 + 0) ^ cx);
        int s1_ = row + (SWZ(u * 4 + 1) ^ cx);
        int s2_ = row + (SWZ(u * 4 + 2) ^ cx);
        int s3_ = row + (SWZ(u * 4 + 3) ^ cx);
        size_t go = (size_t)(h * TT + t0 + rr) * DQK + ch * 16 + kk0h * 8;
        uint4 vh = *(const uint4*)&g_qh[go];
        uint4 vl = *(const uint4*)&g_ql[go];
        smw[SQH + s0_ * 4 + reg] = vh.x;
        smw[SQH + s1_ * 4 + reg] = vh.y;
        smw[SQH + s2_ * 4 + reg] = vh.z;
        smw[SQH + s3_ * 4 + reg] = vh.w;
        smw[SQL + s0_ * 4 + reg] = vl.x;
        smw[SQL + s1_ * 4 + reg] = vl.y;
        smw[SQL + s2_ * 4 + reg] = vl.z;
        smw[SQL + s3_ * 4 + reg] = vl.w;
    }

    float mA = -1.0e30f, mB = -1.0e30f, lA = 0.f, lB = 0.f;
    float O[16][4];
#pragma unroll
    for (int n = 0; n < 16; n++)
#pragma unroll
        for (int e = 0; e < 4; e++) O[n][e] = 0.f;

    for (int sb = 0; sb < nsteps; sb++) {
        const int s0 = sb * 64;
        __syncthreads();

        // ---- stage K hi fragments ----
#pragma unroll
        for (int i = 0; i < 6; i++) {
            int idx = tid + i * 256;
            int sr = idx / 24, u24 = idx % 24;
            int ch = u24 >> 1, kk0h = u24 & 1;
            int nt = sr >> 3, u = sr & 7;
            int reg = kk0h;
            int row = (ch * 8 + nt) * 32, cx = ch & 7;
            int s0_ = row + (SWZ(u * 4 + 0) ^ cx);
            int s1_ = row + (SWZ(u * 4 + 1) ^ cx);
            int s2_ = row + (SWZ(u * 4 + 2) ^ cx);
            int s3_ = row + (SWZ(u * 4 + 3) ^ cx);
            size_t go = (size_t)(h * TT + s0 + sr) * DQK + ch * 16 + kk0h * 8;
            uint4 vh = *(const uint4*)&g_kh[go];
            smw[SKH + s0_ * 2 + reg] = vh.x;
            smw[SKH + s1_ * 2 + reg] = vh.y;
            smw[SKH + s2_ * 2 + reg] = vh.z;
            smw[SKH + s3_ * 2 + reg] = vh.w;
        }
        // ---- stage V hi fragments ----
#pragma unroll
        for (int i = 0; i < 4; i++) {
            int idx = tid + i * 256;
            int v = idx >> 3, u8 = idx & 7;
            int ch = u8 >> 1, kk0h = u8 & 1;
            int nt = v >> 3, u = v & 7;
            int reg = kk0h;
            int row = (ch * 16 + nt) * 32, cx = ch;
            int s0_ = row + (SWZ(u * 4 + 0) ^ cx);
            int s1_ = row + (SWZ(u * 4 + 1) ^ cx);
            int s2_ = row + (SWZ(u * 4 + 2) ^ cx);
            int s3_ = row + (SWZ(u * 4 + 3) ^ cx);
            size_t go = (size_t)(h * DV + v) * TT + s0 + ch * 16 + kk0h * 8;
            uint4 vv = *(const uint4*)&g_vth[go];
            smw[SVH + s0_ * 2 + reg] = vv.x;
            smw[SVH + s1_ * 2 + reg] = vv.y;
            smw[SVH + s2_ * 2 + reg] = vv.z;
            smw[SVH + s3_ * 2 + reg] = vv.w;
        }
        __syncthreads();

        if (s0 > t0 + w * 16 + 15) continue;   // warp tile fully masked

        // ---- S = Q K^T (2 passes: QhKh + QlKh) ----
        float S[8][4];
#pragma unroll
        for (int n = 0; n < 8; n++)
#pragma unroll
            for (int e = 0; e < 4; e++) S[n][e] = 0.f;

#pragma unroll 1
        for (int ch = 0; ch < 12; ch++) {
            int lsw = laneSw ^ (ch & 7);
            uint32_t ab = (uint32_t)(((ch * 8 + w) * 32 + lsw) * 4);
            uint4 aH4 = *(const uint4*)&smw[SQH + ab];
            uint4 aL4 = *(const uint4*)&smw[SQL + ab];
            uint32_t aH[4] = {aH4.x, aH4.y, aH4.z, aH4.w};
            uint32_t aL[4] = {aL4.x, aL4.y, aL4.z, aL4.w};
#pragma unroll
            for (int nt = 0; nt < 8; nt++) {
                uint32_t kb = (uint32_t)(((ch * 8 + nt) * 32 + lsw) * 2);
                uint2 bH = *(const uint2*)&smw[SKH + kb];
                uint32_t bh[2] = {bH.x, bH.y};
                mma16816(S[nt], aH, bh);
                mma16816(S[nt], aL, bh);
            }
        }

        // ---- scale + causal mask ----
        const int rowA = t0 + w * 16 + gr;
        const bool msk = (s0 + 63 > rowA);
#pragma unroll
        for (int nt = 0; nt < 8; nt++) {
            int col = s0 + nt * 8 + 2 * tg;
#pragma unroll
            for (int e = 0; e < 2; e++) {
                float xA = S[nt][e] * ATT_SCALE;
                float xB = S[nt][2 + e] * ATT_SCALE;
                if (msk) {
                    if (col + e > rowA) xA = -1.0e30f;
                    if (col + e > rowA + 8) xB = -1.0e30f;
                }
                S[nt][e] = xA;
                S[nt][2 + e] = xB;
            }
        }

        // ---- online softmax ----
        float pmA = -1.0e30f, pmB = -1.0e30f;
#pragma unroll
        for (int nt = 0; nt < 8; nt++) {
            pmA = fmaxf(pmA, fmaxf(S[nt][0], S[nt][1]));
            pmB = fmaxf(pmB, fmaxf(S[nt][2], S[nt][3]));
        }
        pmA = fmaxf(pmA, __shfl_xor_sync(0xffffffffu, pmA, 1));
        pmA = fmaxf(pmA, __shfl_xor_sync(0xffffffffu, pmA, 2));
        pmB = fmaxf(pmB, __shfl_xor_sync(0xffffffffu, pmB, 1));
        pmB = fmaxf(pmB, __shfl_xor_sync(0xffffffffu, pmB, 2));
        float mnA = fmaxf(mA, pmA), mnB = fmaxf(mB, pmB);
        float aAf = __expf(mA - mnA), aBf = __expf(mB - mnB);
        float sA = 0.f, sB = 0.f;
#pragma unroll
        for (int nt = 0; nt < 8; nt++) {
            S[nt][0] = __expf(S[nt][0] - mnA);
            S[nt][1] = __expf(S[nt][1] - mnA);
            S[nt][2] = __expf(S[nt][2] - mnB);
            S[nt][3] = __expf(S[nt][3] - mnB);
            sA += S[nt][0] + S[nt][1];
            sB += S[nt][2] + S[nt][3];
        }
        sA += __shfl_xor_sync(0xffffffffu, sA, 1);
        sA += __shfl_xor_sync(0xffffffffu, sA, 2);
        sB += __shfl_xor_sync(0xffffffffu, sB, 1);
        sB += __shfl_xor_sync(0xffffffffu, sB, 2);
        lA = lA * aAf + sA; mA = mnA;
        lB = lB * aBf + sB; mB = mnB;
#pragma unroll
        for (int n = 0; n < 16; n++) {
            O[n][0] *= aAf; O[n][1] *= aAf;
            O[n][2] *= aBf; O[n][3] *= aBf;
        }

        // ---- O += P V ----
#pragma unroll 1
        for (int c = 0; c < 4; c++) {
            uint32_t aPh[4], aPl[4];
#pragma unroll
            for (int q2 = 0; q2 < 2; q2++)
#pragma unroll
                for (int pr = 0; pr < 2; pr++)
                    split2pack(S[2 * c + q2][pr * 2], S[2 * c + q2][pr * 2 + 1],
                               aPh[q2 * 2 + pr], aPl[q2 * 2 + pr]);
            int lswv = laneSw ^ c;
#pragma unroll
            for (int nt = 0; nt < 16; nt++) {
                uint32_t vb = (uint32_t)(((c * 16 + nt) * 32 + lswv) * 2);
                uint2 bV = *(const uint2*)&smw[SVH + vb];
                uint32_t b2[2] = {bV.x, bV.y};
                mma16816(O[nt], aPh, b2);
                mma16816(O[nt], aPl, b2);
            }
        }
    }

    // ---- epilogue ----
    const float iA = 1.f / lA, iB = 1.f / lB;
    const int rowA = t0 + w * 16 + gr;
#pragma unroll
    for (int nt = 0; nt < 16; nt++) {
        int col = h * DV + nt * 8 + 2 * tg;
        *(float2*)&out[(size_t)rowA * (HH * DV) + col] =
            make_float2(O[nt][0] * iA, O[nt][1] * iA);
        *(float2*)&out[(size_t)(rowA + 8) * (HH * DV) + col] =
            make_float2(O[nt][2] * iB, O[nt][3] * iB);
    }
}

// ---------------------------------------------------------------------------
extern "C" void kernel_launch(void* const* d_in, const int* in_sizes, int n_in,
                              void* d_out, int out_size) {
    const float* q   = (const float*)d_in[0];   // (T, H, 192)
    const float* kc  = (const float*)d_in[1];   // (T, 512)
    const float* kpe = (const float*)d_in[2];   // (T, 64)
    const float* wkv = (const float*)d_in[3];   // (512, 4096)
    const float* wuv = (const float*)d_in[4];   // (H, 512, 128)
    float* out = (float*)d_out;                 // (T, 2048)

    prep_kernel<<<NB_TOTAL, 256>>>(kc, wkv, wuv, kpe, q);
    prolog_gemm_kernel<<<dim3(32, 16), 128>>>();

    cudaFuncSetAttribute(flash_mma_kernel, cudaFuncAttributeMaxDynamicSharedMemorySize,
                         FLASH_SMEM_BYTES);
    flash_mma_kernel<<<256, 256, FLASH_SMEM_BYTES>>>(out);
}